// round 13
// baseline (speedup 1.0000x reference)
#include <cuda_runtime.h>
#include <cuda_fp16.h>
#include <math_constants.h>
#include <cstdint>
#include <cstddef>
#include <cstring>

// ---------------------------------------------------------------------------
// Problem constants
// ---------------------------------------------------------------------------
#define BATCH   8
#define NMEDIA  8192
#define SLAT    64
#define HEADS   8
#define NSPLIT  33

// ---------------------------------------------------------------------------
// Scratch (device globals)
// ---------------------------------------------------------------------------
__device__ float    g_latproj[(size_t)512 * 1536];                  // [q | k | v] fp32
__device__ __half   g_kvmed [(size_t)BATCH * NMEDIA * 1024];        // fp16 KV cache
__device__ float    g_opart [(size_t)64 * NSPLIT * 64 * 64];
__device__ float    g_mpart [(size_t)64 * NSPLIT * 64];
__device__ float    g_lpart [(size_t)64 * NSPLIT * 64];
__device__ float    g_attno [(size_t)512 * 512];
__device__ __half   g_Wlat  [(size_t)1536 * 512];   // [0.125*g_l*Wq | g_l*Wkv]^T fp16
__device__ __half   g_Wmed  [(size_t)1024 * 512];   // [g_m*Wkv]^T fp16
__device__ __half   g_WoT   [(size_t)512 * 512];    // Wo^T fp16
__device__ float    g_c1lat[1536], g_c2lat[1536];
__device__ float    g_c1med[1024], g_c2med[1024];

// ---------------------------------------------------------------------------
// Helpers
// ---------------------------------------------------------------------------
__device__ __forceinline__ uint32_t pack_h2(float lo, float hi) {
    __half2 h = __floats2half2_rn(lo, hi);
    return *(uint32_t*)&h;
}

__device__ __forceinline__ void mma_f16(float* c, const uint32_t* a, const uint32_t* b) {
    asm volatile(
        "mma.sync.aligned.m16n8k16.row.col.f32.f16.f16.f32 "
        "{%0,%1,%2,%3},{%4,%5,%6,%7},{%8,%9},{%0,%1,%2,%3};"
        : "+f"(c[0]), "+f"(c[1]), "+f"(c[2]), "+f"(c[3])
        : "r"(a[0]), "r"(a[1]), "r"(a[2]), "r"(a[3]), "r"(b[0]), "r"(b[1]));
}

__device__ __forceinline__ void cp16(void* smem, const void* gmem) {
    uint32_t a = (uint32_t)__cvta_generic_to_shared(smem);
    asm volatile("cp.async.cg.shared.global [%0], [%1], 16;" :: "r"(a), "l"(gmem));
}
#define CP_COMMIT() asm volatile("cp.async.commit_group;")
#define CP_WAIT0()  asm volatile("cp.async.wait_group 0;" ::: "memory")

// ---------------------------------------------------------------------------
// Weight prep (R12-passing): transpose + g-fold + scale-fold + fp16 convert.
// ---------------------------------------------------------------------------
__global__ void __launch_bounds__(256)
prep_w(const float* __restrict__ Wq, const float* __restrict__ Wkv,
       const float* __restrict__ Wo, const float* __restrict__ gl,
       const float* __restrict__ gm)
{
    const float* W; __half* WT; const float* gv; int nc; float scale = 1.f;
    switch (blockIdx.z) {
        case 0:  W = Wq;  WT = g_Wlat;             gv = gl;      nc = 512;  scale = 0.125f; break;
        case 1:  W = Wkv; WT = g_Wlat + 512 * 512; gv = gl;      nc = 1024; break;
        case 2:  W = Wkv; WT = g_Wmed;             gv = gm;      nc = 1024; break;
        default: W = Wo;  WT = g_WoT;              gv = nullptr; nc = 512;  break;
    }
    const int c0 = blockIdx.x * 64;
    if (c0 >= nc) return;
    const int k0 = blockIdx.y * 64;
    const int tid = threadIdx.x;

    __shared__ float ts[64][65];
    #pragma unroll
    for (int it = 0; it < 16; ++it) {
        int e = tid + it * 256;
        int k = e >> 6, c = e & 63;
        float gk = gv ? gv[k0 + k] * scale : scale;
        ts[k][c] = W[(size_t)(k0 + k) * nc + c0 + c] * gk;
    }
    __syncthreads();
    #pragma unroll
    for (int it = 0; it < 16; ++it) {
        int e = tid + it * 256;
        int c = e >> 6, k = e & 63;
        WT[(size_t)(c0 + c) * 512 + (k0 + k)] = __float2half_rn(ts[k][c]);
    }
}

// ---------------------------------------------------------------------------
// Column-vector prep (R12-passing).
// ---------------------------------------------------------------------------
__global__ void __launch_bounds__(256)
prep_c(const float* __restrict__ Wq, const float* __restrict__ Wkv,
       const float* __restrict__ bq, const float* __restrict__ bkv,
       const float* __restrict__ bl, const float* __restrict__ bm)
{
    const int bx = blockIdx.x;
    const float *W, *bv, *bias;
    const __half* WT;
    float *c1o, *c2o;
    int nc, srcCol, colBase;
    float scale = 1.f;

    if (bx < 24) {
        colBase = bx * 64;
        if (colBase < 512) { W = Wq;  nc = 512;  bias = bq;  srcCol = colBase;       scale = 0.125f; }
        else               { W = Wkv; nc = 1024; bias = bkv; srcCol = colBase - 512; }
        bv = bl; WT = g_Wlat; c1o = g_c1lat; c2o = g_c2lat;
    } else {
        colBase = (bx - 24) * 64;
        W = Wkv; nc = 1024; bias = bkv; srcCol = colBase;
        bv = bm; WT = g_Wmed; c1o = g_c1med; c2o = g_c2med;
    }

    const int tid = threadIdx.x;
    {
        const int c = tid & 63, kq = tid >> 6;
        float part = 0.f;
        for (int k = kq; k < 512; k += 4)
            part = fmaf(bv[k], W[(size_t)k * nc + srcCol + c], part);
        __shared__ float red[4][64];
        red[kq][c] = part;
        __syncthreads();
        if (tid < 64) {
            float s = red[0][tid] + red[1][tid] + red[2][tid] + red[3][tid];
            c2o[colBase + tid] = (s + bias[srcCol + tid]) * scale;
        }
    }
    {
        const int warp = tid >> 5, lane = tid & 31;
        #pragma unroll
        for (int cc = 0; cc < 8; ++cc) {
            int col = colBase + warp * 8 + cc;
            const __half* p = WT + (size_t)col * 512;
            float s = 0.f;
            #pragma unroll
            for (int u = 0; u < 16; ++u)
                s += __half2float(p[lane + 32 * u]);
            #pragma unroll
            for (int o = 16; o > 0; o >>= 1)
                s += __shfl_xor_sync(0xffffffffu, s, o);
            if (lane == 0) c1o[col] = s;
        }
    }
}

// ---------------------------------------------------------------------------
// Unified big GEMM: 128x128 tile, 256 threads (8 warps 2x4, warp tile 64x32),
// 2 CTAs/SM (the point of this round), K-chunk 32, double-buffered
// (A register prefetch + LN stats, B cp.async), stride-20 smem rows.
// Grid: [0,4096) media KV (fp16 out, mask-skipped), [4096,4144) latproj.
// ---------------------------------------------------------------------------
#define NSTR 20
#define TBUF (128 * NSTR)
#define BIG_SMEM (4 * TBUF * (int)sizeof(uint32_t))   // 40960 B

__global__ void __launch_bounds__(256, 2)
gemm_big(const float* __restrict__ x, const float* __restrict__ lat,
         const int* __restrict__ idx)
{
    const int bid = blockIdx.x;
    const float* src; const __half* WT;
    float* outf = nullptr; __half* outh = nullptr;
    const float *c1, *c2;
    int nc;
    bool media;
    if (bid < 4096) {
        const int b = bid >> 9, rr = (bid >> 3) & 63, cc = bid & 7;
        const int rowBase = rr * 128;
        if (rowBase >= idx[b] * 256) return;
        src  = x + ((size_t)b * NMEDIA + rowBase) * 512;
        WT   = g_Wmed + (size_t)(cc * 128) * 512;
        outh = g_kvmed + ((size_t)b * NMEDIA + rowBase) * 1024 + cc * 128;
        c1 = g_c1med + cc * 128; c2 = g_c2med + cc * 128;
        nc = 1024; media = true;
    } else {
        const int l = bid - 4096;        // 0..47
        const int rr = l / 12, cc = l % 12;
        src  = lat + (size_t)(rr * 128) * 512;
        WT   = g_Wlat + (size_t)(cc * 128) * 512;
        outf = g_latproj + (size_t)(rr * 128) * 1536 + cc * 128;
        c1 = g_c1lat + cc * 128; c2 = g_c2lat + cc * 128;
        nc = 1536; media = false;
    }

    extern __shared__ uint32_t dyn[];
    uint32_t* As = dyn;                  // [2][TBUF]
    uint32_t* Bs = dyn + 2 * TBUF;       // [2][TBUF]
    __shared__ float2 st[128];

    const int tid = threadIdx.x;
    const int am = tid >> 3, akq = (tid & 7) * 4;
    const int aw = (tid & 7) * 2;

    float4 rv[4];
    float sm[4] = {0.f, 0.f, 0.f, 0.f};
    float sq[4] = {0.f, 0.f, 0.f, 0.f};

    auto lda = [&](int k0) {
        #pragma unroll
        for (int u = 0; u < 4; ++u)
            rv[u] = *(const float4*)(src + (size_t)(am + 32 * u) * 512 + k0 + akq);
    };
    auto sta = [&](int buf) {
        #pragma unroll
        for (int u = 0; u < 4; ++u) {
            float4 v = rv[u];
            sm[u] += v.x + v.y + v.z + v.w;
            sq[u] = fmaf(v.x, v.x, sq[u]); sq[u] = fmaf(v.y, v.y, sq[u]);
            sq[u] = fmaf(v.z, v.z, sq[u]); sq[u] = fmaf(v.w, v.w, sq[u]);
            uint2 t;
            t.x = pack_h2(v.x, v.y);
            t.y = pack_h2(v.z, v.w);
            *(uint2*)&As[buf * TBUF + (am + 32 * u) * NSTR + aw] = t;
        }
    };
    auto cpb = [&](int k0, int buf) {    // k0 in half units
        #pragma unroll
        for (int u = 0; u < 2; ++u) {
            int e = tid + u * 256;       // 0..511
            int row = e >> 2, seg = e & 3;
            cp16(&Bs[buf * TBUF + row * NSTR + seg * 4],
                 WT + (size_t)row * 512 + k0 + seg * 8);
        }
        CP_COMMIT();
    };

    const int warp = tid >> 5, lane = tid & 31;
    const int wm = warp >> 2, wn = warp & 3;
    const int qr = lane >> 2, qc = lane & 3;

    float acc[4][4][4];
    #pragma unroll
    for (int i = 0; i < 4; ++i)
        #pragma unroll
        for (int j = 0; j < 4; ++j)
            #pragma unroll
            for (int r = 0; r < 4; ++r) acc[i][j][r] = 0.f;

    lda(0); sta(0); cpb(0, 0);

    for (int kc = 0; kc < 16; ++kc) {
        const int buf = kc & 1;
        CP_WAIT0();
        __syncthreads();

        const bool nxt = (kc < 15);
        if (nxt) { lda((kc + 1) * 32); cpb((kc + 1) * 32, buf ^ 1); }

        const uint32_t* Ab = As + buf * TBUF;
        const uint32_t* Bb = Bs + buf * TBUF;
        #pragma unroll
        for (int ks = 0; ks < 2; ++ks) {
            uint32_t a[4][4], bb[4][2];
            #pragma unroll
            for (int i = 0; i < 4; ++i) {
                int r0 = wm * 64 + i * 16 + qr;
                a[i][0] = Ab[(r0    ) * NSTR + ks * 8 + qc    ];
                a[i][1] = Ab[(r0 + 8) * NSTR + ks * 8 + qc    ];
                a[i][2] = Ab[(r0    ) * NSTR + ks * 8 + qc + 4];
                a[i][3] = Ab[(r0 + 8) * NSTR + ks * 8 + qc + 4];
            }
            #pragma unroll
            for (int j = 0; j < 4; ++j) {
                int cb = wn * 32 + j * 8 + qr;
                bb[j][0] = Bb[cb * NSTR + ks * 8 + qc    ];
                bb[j][1] = Bb[cb * NSTR + ks * 8 + qc + 4];
            }
            #pragma unroll
            for (int i = 0; i < 4; ++i)
                #pragma unroll
                for (int j = 0; j < 4; ++j)
                    mma_f16(acc[i][j], a[i], bb[j]);
        }

        if (nxt) sta(buf ^ 1);
    }

    // ---- LN stats reduce (8-lane groups share rows) ----
    #pragma unroll
    for (int u = 0; u < 4; ++u) {
        #pragma unroll
        for (int o = 1; o < 8; o <<= 1) {
            sm[u] += __shfl_xor_sync(0xffffffffu, sm[u], o);
            sq[u] += __shfl_xor_sync(0xffffffffu, sq[u], o);
        }
    }
    if ((tid & 7) == 0) {
        #pragma unroll
        for (int u = 0; u < 4; ++u) {
            float mu  = sm[u] * (1.f / 512.f);
            float var = fmaf(-mu, mu, sq[u] * (1.f / 512.f));
            st[am + 32 * u] = make_float2(mu, rsqrtf(var + 1e-5f));
        }
    }
    __syncthreads();

    // ---- epilogue: out = rs*acc - rs*mu*c1 + c2 ----
    #pragma unroll
    for (int i = 0; i < 4; ++i) {
        int r0 = wm * 64 + i * 16 + qr;
        float2 s0 = st[r0], s1 = st[r0 + 8];
        float rs0 = s0.y, t0 = s0.y * s0.x;
        float rs1 = s1.y, t1 = s1.y * s1.x;
        #pragma unroll
        for (int j = 0; j < 4; ++j) {
            int col = wn * 32 + j * 8 + qc * 2;
            float2 c1v = *(const float2*)(c1 + col);
            float2 c2v = *(const float2*)(c2 + col);
            float2 o0, o1;
            o0.x = fmaf(acc[i][j][0], rs0, fmaf(-t0, c1v.x, c2v.x));
            o0.y = fmaf(acc[i][j][1], rs0, fmaf(-t0, c1v.y, c2v.y));
            o1.x = fmaf(acc[i][j][2], rs1, fmaf(-t1, c1v.x, c2v.x));
            o1.y = fmaf(acc[i][j][3], rs1, fmaf(-t1, c1v.y, c2v.y));
            if (media) {
                *(__half2*)(outh + (size_t)(r0    ) * 1024 + col) = __floats2half2_rn(o0.x, o0.y);
                *(__half2*)(outh + (size_t)(r0 + 8) * 1024 + col) = __floats2half2_rn(o1.x, o1.y);
            } else {
                *(float2*)(outf + (size_t)(r0    ) * nc + col) = o0;
                *(float2*)(outf + (size_t)(r0 + 8) * nc + col) = o1;
            }
        }
    }
}

// ---------------------------------------------------------------------------
// Output projection GEMM, fp16 (R12-passing).
// ---------------------------------------------------------------------------
#define OBUF (128 * NSTR)
#define OUT_SMEM (4 * OBUF * (int)sizeof(uint32_t))

__global__ void __launch_bounds__(256, 2)
gemm_out(const float* __restrict__ src, const float* __restrict__ bias,
         float* __restrict__ out)
{
    const int rowBase = (blockIdx.x >> 2) * 128;
    const int colBase = (blockIdx.x & 3) * 128;
    const float* srcB = src + (size_t)rowBase * 512;
    float* outB = out + (size_t)rowBase * 512;

    extern __shared__ uint32_t dyn2[];
    uint32_t* As = dyn2;
    uint32_t* Bs = dyn2 + 2 * OBUF;

    const int tid = threadIdx.x;
    const int am = tid >> 3, akq = (tid & 7) * 4;
    const int aw = (tid & 7) * 2;
    float4 rv[4];

    auto lda = [&](int k0) {
        #pragma unroll
        for (int u = 0; u < 4; ++u)
            rv[u] = *(const float4*)(srcB + (size_t)(am + 32 * u) * 512 + k0 + akq);
    };
    auto sta = [&](int buf) {
        #pragma unroll
        for (int u = 0; u < 4; ++u) {
            float4 v = rv[u];
            uint2 t;
            t.x = pack_h2(v.x, v.y);
            t.y = pack_h2(v.z, v.w);
            *(uint2*)&As[buf * OBUF + (am + 32 * u) * NSTR + aw] = t;
        }
    };
    auto cpb = [&](int k0, int buf) {
        #pragma unroll
        for (int u = 0; u < 2; ++u) {
            int e = tid + u * 256;
            int row = e >> 2, seg = e & 3;
            cp16(&Bs[buf * OBUF + row * NSTR + seg * 4],
                 g_WoT + (size_t)(colBase + row) * 512 + k0 + seg * 8);
        }
        CP_COMMIT();
    };

    const int warp = tid >> 5, lane = tid & 31;
    const int wm = warp >> 2, wn = warp & 3;
    const int qr = lane >> 2, qc = lane & 3;

    float acc[4][4][4];
    #pragma unroll
    for (int i = 0; i < 4; ++i)
        #pragma unroll
        for (int j = 0; j < 4; ++j)
            #pragma unroll
            for (int r = 0; r < 4; ++r) acc[i][j][r] = 0.f;

    lda(0); sta(0); cpb(0, 0);

    for (int kc = 0; kc < 16; ++kc) {
        const int buf = kc & 1;
        CP_WAIT0();
        __syncthreads();
        const bool nxt = (kc < 15);
        if (nxt) { lda((kc + 1) * 32); cpb((kc + 1) * 32, buf ^ 1); }

        const uint32_t* Ab = As + buf * OBUF;
        const uint32_t* Bb = Bs + buf * OBUF;
        #pragma unroll
        for (int ks = 0; ks < 2; ++ks) {
            uint32_t a[4][4], bb[4][2];
            #pragma unroll
            for (int i = 0; i < 4; ++i) {
                int r0 = wm * 64 + i * 16 + qr;
                a[i][0] = Ab[(r0    ) * NSTR + ks * 8 + qc    ];
                a[i][1] = Ab[(r0 + 8) * NSTR + ks * 8 + qc    ];
                a[i][2] = Ab[(r0    ) * NSTR + ks * 8 + qc + 4];
                a[i][3] = Ab[(r0 + 8) * NSTR + ks * 8 + qc + 4];
            }
            #pragma unroll
            for (int j = 0; j < 4; ++j) {
                int cb = wn * 32 + j * 8 + qr;
                bb[j][0] = Bb[cb * NSTR + ks * 8 + qc    ];
                bb[j][1] = Bb[cb * NSTR + ks * 8 + qc + 4];
            }
            #pragma unroll
            for (int i = 0; i < 4; ++i)
                #pragma unroll
                for (int j = 0; j < 4; ++j)
                    mma_f16(acc[i][j], a[i], bb[j]);
        }
        if (nxt) sta(buf ^ 1);
    }

    #pragma unroll
    for (int i = 0; i < 4; ++i) {
        int r0 = wm * 64 + i * 16 + qr;
        #pragma unroll
        for (int j = 0; j < 4; ++j) {
            int col = colBase + wn * 32 + j * 8 + qc * 2;
            float2 bi = *(const float2*)(bias + col);
            *(float2*)(outB + (size_t)(r0    ) * 512 + col) =
                make_float2(acc[i][j][0] + bi.x, acc[i][j][1] + bi.y);
            *(float2*)(outB + (size_t)(r0 + 8) * 512 + col) =
                make_float2(acc[i][j][2] + bi.x, acc[i][j][3] + bi.y);
        }
    }
}

// ---------------------------------------------------------------------------
// fp16 split-KV flash attention with software pipelining (R12-passing).
// ---------------------------------------------------------------------------
#define ASTR 36
#define ABLK (64 * ASTR)
#define ATTN_SMEM (6 * ABLK * (int)sizeof(uint32_t))   // 55296 B

__global__ void __launch_bounds__(128)
attn_split_f16(const float* __restrict__ latproj, const int* __restrict__ indices)
{
    const int b = blockIdx.z, h = blockIdx.y, s = blockIdx.x;
    const int vis = indices[b];
    const bool is_lat = (s == 32);
    if (!is_lat && s >= vis) return;

    extern __shared__ uint32_t smw[];
    uint32_t* Qs = smw;                  // [64][36]
    uint32_t* Ps = Qs + ABLK;            // [64][36]
    uint32_t* Ks = Ps + ABLK;            // [2][64][36]
    uint32_t* Vp = Ks + 2 * ABLK;        // [2][64][36] d-major, half2 along j

    const int tid = threadIdx.x, warp = tid >> 5, lane = tid & 31;
    const int qr = lane >> 2, qc = lane & 3;
    const int r0 = warp * 16 + qr;

    #pragma unroll
    for (int it = 0; it < 4; ++it) {
        int e = tid + it * 128;
        int r = e >> 3, c8 = (e & 7) * 8;
        const float* qp = latproj + ((size_t)b * 64 + r) * 1536 + h * 64 + c8;
        float4 v0 = *(const float4*)qp;
        float4 v1 = *(const float4*)(qp + 4);
        uint4 t;
        t.x = pack_h2(v0.x, v0.y); t.y = pack_h2(v0.z, v0.w);
        t.z = pack_h2(v1.x, v1.y); t.w = pack_h2(v1.z, v1.w);
        *(uint4*)&Qs[r * ASTR + (e & 7) * 4] = t;
    }

    const __half* kvb_h = g_kvmed + ((size_t)b * NMEDIA + (size_t)s * 256) * 1024;
    const float*  kvb_f = latproj + (size_t)b * 64 * 1536;
    const int koff_h = h * 64, voff_h = 512 + h * 64;
    const int koff_f = 512 + h * 64, voff_f = 1024 + h * 64;
    const int nch = is_lat ? 1 : 4;

    uint4 kreg[4], vreg[4];
    auto loadregs = [&](int ch) {
        #pragma unroll
        for (int it = 0; it < 4; ++it) {
            int e = tid + it * 128;
            int j = e >> 3, d0 = (e & 7) * 8;
            if (is_lat) {
                const float* rp = kvb_f + (size_t)j * 1536;
                __half kh[8], vh[8];
                #pragma unroll
                for (int i = 0; i < 8; ++i) {
                    kh[i] = __float2half_rn(rp[koff_f + d0 + i]);
                    vh[i] = __float2half_rn(rp[voff_f + d0 + i]);
                }
                kreg[it] = *(const uint4*)kh;
                vreg[it] = *(const uint4*)vh;
            } else {
                const __half* rp = kvb_h + (size_t)(ch * 64 + j) * 1024;
                kreg[it] = *(const uint4*)(rp + koff_h + d0);
                vreg[it] = *(const uint4*)(rp + voff_h + d0);
            }
        }
    };
    auto storeregs = [&](int buf) {
        uint32_t* Kb = Ks + buf * ABLK;
        __half*   Vb = (__half*)(Vp + buf * ABLK);
        #pragma unroll
        for (int it = 0; it < 4; ++it) {
            int e = tid + it * 128;
            int j = e >> 3, w4 = e & 7, d0 = w4 * 8;
            *(uint4*)&Kb[j * ASTR + w4 * 4] = kreg[it];
            const __half* vh = (const __half*)&vreg[it];
            #pragma unroll
            for (int i = 0; i < 8; ++i)
                Vb[(d0 + i) * (2 * ASTR) + j] = vh[i];
        }
    };

    float m0 = -CUDART_INF_F, m1 = -CUDART_INF_F, l0 = 0.f, l1 = 0.f;
    float o[8][4];
    #pragma unroll
    for (int nf = 0; nf < 8; ++nf)
        #pragma unroll
        for (int r = 0; r < 4; ++r) o[nf][r] = 0.f;

    loadregs(0);
    storeregs(0);
    __syncthreads();

    for (int ch = 0; ch < nch; ++ch) {
        const int buf = ch & 1;
        const bool nxt = (ch + 1 < nch);
        if (nxt) loadregs(ch + 1);

        const uint32_t* Kb = Ks + buf * ABLK;
        const uint32_t* Vb = Vp + buf * ABLK;

        float sacc[8][4] = {};
        #pragma unroll
        for (int ks = 0; ks < 4; ++ks) {
            uint32_t a[4];
            a[0] = Qs[(r0    ) * ASTR + ks * 8 + qc    ];
            a[1] = Qs[(r0 + 8) * ASTR + ks * 8 + qc    ];
            a[2] = Qs[(r0    ) * ASTR + ks * 8 + qc + 4];
            a[3] = Qs[(r0 + 8) * ASTR + ks * 8 + qc + 4];
            #pragma unroll
            for (int nf = 0; nf < 8; ++nf) {
                uint32_t bb[2];
                bb[0] = Kb[(nf * 8 + qr) * ASTR + ks * 8 + qc    ];
                bb[1] = Kb[(nf * 8 + qr) * ASTR + ks * 8 + qc + 4];
                mma_f16(sacc[nf], a, bb);
            }
        }

        float rm0 = -CUDART_INF_F, rm1 = -CUDART_INF_F;
        #pragma unroll
        for (int nf = 0; nf < 8; ++nf) {
            rm0 = fmaxf(rm0, fmaxf(sacc[nf][0], sacc[nf][1]));
            rm1 = fmaxf(rm1, fmaxf(sacc[nf][2], sacc[nf][3]));
        }
        rm0 = fmaxf(rm0, __shfl_xor_sync(0xffffffffu, rm0, 1));
        rm0 = fmaxf(rm0, __shfl_xor_sync(0xffffffffu, rm0, 2));
        rm1 = fmaxf(rm1, __shfl_xor_sync(0xffffffffu, rm1, 1));
        rm1 = fmaxf(rm1, __shfl_xor_sync(0xffffffffu, rm1, 2));
        float mn0 = fmaxf(m0, rm0), mn1 = fmaxf(m1, rm1);
        float cc0 = __expf(m0 - mn0), cc1 = __expf(m1 - mn1);
        float s0 = 0.f, s1 = 0.f;
        #pragma unroll
        for (int nf = 0; nf < 8; ++nf) {
            float p00 = __expf(sacc[nf][0] - mn0);
            float p01 = __expf(sacc[nf][1] - mn0);
            float p10 = __expf(sacc[nf][2] - mn1);
            float p11 = __expf(sacc[nf][3] - mn1);
            s0 += p00 + p01; s1 += p10 + p11;
            Ps[(r0    ) * ASTR + nf * 4 + qc] = pack_h2(p00, p01);
            Ps[(r0 + 8) * ASTR + nf * 4 + qc] = pack_h2(p10, p11);
            o[nf][0] *= cc0; o[nf][1] *= cc0;
            o[nf][2] *= cc1; o[nf][3] *= cc1;
        }
        s0 += __shfl_xor_sync(0xffffffffu, s0, 1);
        s0 += __shfl_xor_sync(0xffffffffu, s0, 2);
        s1 += __shfl_xor_sync(0xffffffffu, s1, 1);
        s1 += __shfl_xor_sync(0xffffffffu, s1, 2);
        m0 = mn0; m1 = mn1;
        l0 = fmaf(l0, cc0, s0);
        l1 = fmaf(l1, cc1, s1);
        __syncwarp();

        #pragma unroll
        for (int ks = 0; ks < 4; ++ks) {
            uint32_t a[4];
            a[0] = Ps[(r0    ) * ASTR + ks * 8 + qc    ];
            a[1] = Ps[(r0 + 8) * ASTR + ks * 8 + qc    ];
            a[2] = Ps[(r0    ) * ASTR + ks * 8 + qc + 4];
            a[3] = Ps[(r0 + 8) * ASTR + ks * 8 + qc + 4];
            #pragma unroll
            for (int nf = 0; nf < 8; ++nf) {
                uint32_t bb[2];
                bb[0] = Vb[(nf * 8 + qr) * ASTR + ks * 8 + qc    ];
                bb[1] = Vb[(nf * 8 + qr) * ASTR + ks * 8 + qc + 4];
                mma_f16(o[nf], a, bb);
            }
        }

        if (nxt) {
            storeregs(buf ^ 1);
            __syncthreads();
        }
    }

    const size_t pbase = ((size_t)(b * HEADS + h)) * NSPLIT + s;
    float* op = g_opart + pbase * 4096;
    #pragma unroll
    for (int nf = 0; nf < 8; ++nf) {
        *(float2*)&op[(r0    ) * 64 + nf * 8 + qc * 2] = make_float2(o[nf][0], o[nf][1]);
        *(float2*)&op[(r0 + 8) * 64 + nf * 8 + qc * 2] = make_float2(o[nf][2], o[nf][3]);
    }
    if (qc == 0) {
        g_mpart[pbase * 64 + r0    ] = m0;
        g_mpart[pbase * 64 + r0 + 8] = m1;
        g_lpart[pbase * 64 + r0    ] = l0;
        g_lpart[pbase * 64 + r0 + 8] = l1;
    }
}

// ---------------------------------------------------------------------------
// Combine split partials -> attn_out (R12-passing).
// ---------------------------------------------------------------------------
__global__ void __launch_bounds__(256)
attn_combine(const int* __restrict__ indices, float* __restrict__ attn_out)
{
    const int bh = blockIdx.x;
    const int b = bh >> 3, h = bh & 7;
    const int vis = indices[b];
    const int warp = threadIdx.x >> 5, lane = threadIdx.x & 31;
    const int i = blockIdx.y * 8 + warp;

    __shared__ float ws[8][33];
    __shared__ float linv[8];

    const size_t base = (size_t)bh * NSPLIT;

    float m    = (lane < vis) ? g_mpart[(base + lane) * 64 + i] : -CUDART_INF_F;
    float mlat = g_mpart[(base + 32) * 64 + i];
    float mm = fmaxf(m, mlat);
    #pragma unroll
    for (int o = 16; o > 0; o >>= 1)
        mm = fmaxf(mm, __shfl_xor_sync(0xffffffffu, mm, o));

    float w  = (lane < vis) ? __expf(m - mm) : 0.f;
    float wl = __expf(mlat - mm);
    float l  = (lane < vis) ? g_lpart[(base + lane) * 64 + i] * w : 0.f;
    #pragma unroll
    for (int o = 16; o > 0; o >>= 1)
        l += __shfl_xor_sync(0xffffffffu, l, o);
    float ll = g_lpart[(base + 32) * 64 + i] * wl;

    ws[warp][lane] = w;
    if (lane == 0) {
        ws[warp][32] = wl;
        linv[warp] = 1.f / (l + ll);
    }
    __syncwarp();

    const int d = lane * 2;
    float2 v = *(const float2*)(g_opart + (base + 32) * 4096 + i * 64 + d);
    float a0 = v.x * ws[warp][32];
    float a1 = v.y * ws[warp][32];
    for (int s = 0; s < vis; ++s) {
        float wv = ws[warp][s];
        float2 u = *(const float2*)(g_opart + (base + s) * 4096 + i * 64 + d);
        a0 = fmaf(u.x, wv, a0);
        a1 = fmaf(u.y, wv, a1);
    }
    float li = linv[warp];
    *(float2*)(attn_out + ((size_t)b * 64 + i) * 512 + h * 64 + d) =
        make_float2(a0 * li, a1 * li);
}

// ---------------------------------------------------------------------------
// Launch
// ---------------------------------------------------------------------------
extern "C" void kernel_launch(void* const* d_in, const int* in_sizes, int n_in,
                              void* d_out, int out_size)
{
    (void)in_sizes; (void)n_in; (void)out_size;
    const float* x    = (const float*)d_in[0];
    const float* lat  = (const float*)d_in[1];
    const int*   idx  = (const int*)  d_in[2];
    const float* g_m  = (const float*)d_in[3];
    const float* b_m  = (const float*)d_in[4];
    const float* g_l  = (const float*)d_in[5];
    const float* b_l  = (const float*)d_in[6];
    const float* Wq   = (const float*)d_in[7];
    const float* bq   = (const float*)d_in[8];
    const float* Wkv  = (const float*)d_in[9];
    const float* bkv  = (const float*)d_in[10];
    const float* Wo   = (const float*)d_in[11];
    const float* bo   = (const float*)d_in[12];
    float* out = (float*)d_out;

    void *plp, *pattno;
    cudaGetSymbolAddress(&plp,    g_latproj);
    cudaGetSymbolAddress(&pattno, g_attno);

    cudaFuncSetAttribute(gemm_big,
                         cudaFuncAttributeMaxDynamicSharedMemorySize, BIG_SMEM);
    cudaFuncSetAttribute(gemm_out,
                         cudaFuncAttributeMaxDynamicSharedMemorySize, OUT_SMEM);
    cudaFuncSetAttribute(attn_split_f16,
                         cudaFuncAttributeMaxDynamicSharedMemorySize, ATTN_SMEM);

    // weight + column-vector prep
    prep_w<<<dim3(16, 8, 4), 256>>>(Wq, Wkv, Wo, g_l, g_m);
    prep_c<<<40, 256>>>(Wq, Wkv, bq, bkv, b_l, b_m);

    // unified media-KV (fp16 out) + latent projections (128x128, 2 CTAs/SM)
    gemm_big<<<4144, 256, BIG_SMEM>>>(x, lat, idx);

    // attention (fp16 MMA, pipelined KV)
    attn_split_f16<<<dim3(NSPLIT, HEADS, BATCH), 128, ATTN_SMEM>>>(
        (const float*)plp, idx);
    attn_combine<<<dim3(64, 8), 256>>>(idx, (float*)pattno);

    // output projection
    gemm_out<<<16, 256, OUT_SMEM>>>((const float*)pattno, bo, out);
}

// round 14
// speedup vs baseline: 1.0459x; 1.0459x over previous
#include <cuda_runtime.h>
#include <cuda_fp16.h>
#include <math_constants.h>
#include <cstdint>
#include <cstddef>
#include <cstring>

// ---------------------------------------------------------------------------
// Problem constants
// ---------------------------------------------------------------------------
#define BATCH   8
#define NMEDIA  8192
#define SLAT    64
#define HEADS   8
#define NSP     17          // 16 media windows (512 tokens) + 1 latent

// ---------------------------------------------------------------------------
// Scratch (device globals)
// ---------------------------------------------------------------------------
__device__ float    g_latproj[(size_t)512 * 1536];                  // [q | k | v] fp32
__device__ __half   g_kvmed [(size_t)BATCH * NMEDIA * 1024];        // fp16 KV cache
__device__ float    g_opart [(size_t)64 * NSP * 64 * 64];
__device__ float    g_mpart [(size_t)64 * NSP * 64];
__device__ float    g_lpart [(size_t)64 * NSP * 64];
__device__ float    g_attno [(size_t)512 * 512];
__device__ __half   g_Wlat  [(size_t)1536 * 512];   // [0.125*g_l*Wq | g_l*Wkv]^T fp16
__device__ __half   g_Wmed  [(size_t)1024 * 512];   // [g_m*Wkv]^T fp16
__device__ __half   g_WoT   [(size_t)512 * 512];    // Wo^T fp16
__device__ float    g_c1lat[1536], g_c2lat[1536];
__device__ float    g_c1med[1024], g_c2med[1024];

// ---------------------------------------------------------------------------
// Helpers
// ---------------------------------------------------------------------------
__device__ __forceinline__ uint32_t pack_h2(float lo, float hi) {
    __half2 h = __floats2half2_rn(lo, hi);
    return *(uint32_t*)&h;
}

__device__ __forceinline__ void mma_f16(float* c, const uint32_t* a, const uint32_t* b) {
    asm volatile(
        "mma.sync.aligned.m16n8k16.row.col.f32.f16.f16.f32 "
        "{%0,%1,%2,%3},{%4,%5,%6,%7},{%8,%9},{%0,%1,%2,%3};"
        : "+f"(c[0]), "+f"(c[1]), "+f"(c[2]), "+f"(c[3])
        : "r"(a[0]), "r"(a[1]), "r"(a[2]), "r"(a[3]), "r"(b[0]), "r"(b[1]));
}

__device__ __forceinline__ void cp16(void* smem, const void* gmem) {
    uint32_t a = (uint32_t)__cvta_generic_to_shared(smem);
    asm volatile("cp.async.cg.shared.global [%0], [%1], 16;" :: "r"(a), "l"(gmem));
}
#define CP_COMMIT() asm volatile("cp.async.commit_group;")
#define CP_WAIT0()  asm volatile("cp.async.wait_group 0;" ::: "memory")

// ---------------------------------------------------------------------------
// Weight prep (R12-passing): transpose + g-fold + scale-fold + fp16 convert.
// ---------------------------------------------------------------------------
__global__ void __launch_bounds__(256)
prep_w(const float* __restrict__ Wq, const float* __restrict__ Wkv,
       const float* __restrict__ Wo, const float* __restrict__ gl,
       const float* __restrict__ gm)
{
    const float* W; __half* WT; const float* gv; int nc; float scale = 1.f;
    switch (blockIdx.z) {
        case 0:  W = Wq;  WT = g_Wlat;             gv = gl;      nc = 512;  scale = 0.125f; break;
        case 1:  W = Wkv; WT = g_Wlat + 512 * 512; gv = gl;      nc = 1024; break;
        case 2:  W = Wkv; WT = g_Wmed;             gv = gm;      nc = 1024; break;
        default: W = Wo;  WT = g_WoT;              gv = nullptr; nc = 512;  break;
    }
    const int c0 = blockIdx.x * 64;
    if (c0 >= nc) return;
    const int k0 = blockIdx.y * 64;
    const int tid = threadIdx.x;

    __shared__ float ts[64][65];
    #pragma unroll
    for (int it = 0; it < 16; ++it) {
        int e = tid + it * 256;
        int k = e >> 6, c = e & 63;
        float gk = gv ? gv[k0 + k] * scale : scale;
        ts[k][c] = W[(size_t)(k0 + k) * nc + c0 + c] * gk;
    }
    __syncthreads();
    #pragma unroll
    for (int it = 0; it < 16; ++it) {
        int e = tid + it * 256;
        int c = e >> 6, k = e & 63;
        WT[(size_t)(c0 + c) * 512 + (k0 + k)] = __float2half_rn(ts[k][c]);
    }
}

// ---------------------------------------------------------------------------
// Column-vector prep (R12-passing).
// ---------------------------------------------------------------------------
__global__ void __launch_bounds__(256)
prep_c(const float* __restrict__ Wq, const float* __restrict__ Wkv,
       const float* __restrict__ bq, const float* __restrict__ bkv,
       const float* __restrict__ bl, const float* __restrict__ bm)
{
    const int bx = blockIdx.x;
    const float *W, *bv, *bias;
    const __half* WT;
    float *c1o, *c2o;
    int nc, srcCol, colBase;
    float scale = 1.f;

    if (bx < 24) {
        colBase = bx * 64;
        if (colBase < 512) { W = Wq;  nc = 512;  bias = bq;  srcCol = colBase;       scale = 0.125f; }
        else               { W = Wkv; nc = 1024; bias = bkv; srcCol = colBase - 512; }
        bv = bl; WT = g_Wlat; c1o = g_c1lat; c2o = g_c2lat;
    } else {
        colBase = (bx - 24) * 64;
        W = Wkv; nc = 1024; bias = bkv; srcCol = colBase;
        bv = bm; WT = g_Wmed; c1o = g_c1med; c2o = g_c2med;
    }

    const int tid = threadIdx.x;
    {
        const int c = tid & 63, kq = tid >> 6;
        float part = 0.f;
        for (int k = kq; k < 512; k += 4)
            part = fmaf(bv[k], W[(size_t)k * nc + srcCol + c], part);
        __shared__ float red[4][64];
        red[kq][c] = part;
        __syncthreads();
        if (tid < 64) {
            float s = red[0][tid] + red[1][tid] + red[2][tid] + red[3][tid];
            c2o[colBase + tid] = (s + bias[srcCol + tid]) * scale;
        }
    }
    {
        const int warp = tid >> 5, lane = tid & 31;
        #pragma unroll
        for (int cc = 0; cc < 8; ++cc) {
            int col = colBase + warp * 8 + cc;
            const __half* p = WT + (size_t)col * 512;
            float s = 0.f;
            #pragma unroll
            for (int u = 0; u < 16; ++u)
                s += __half2float(p[lane + 32 * u]);
            #pragma unroll
            for (int o = 16; o > 0; o >>= 1)
                s += __shfl_xor_sync(0xffffffffu, s, o);
            if (lane == 0) c1o[col] = s;
        }
    }
}

// ---------------------------------------------------------------------------
// Unified big GEMM (R12-passing, KC=64): 128x256 tile, 256 threads,
// 8 chunks, double-buffered (A register prefetch + LN stats, B cp.async),
// stride-36 smem rows. Grid: [0,2048) media (mask-skipped), [2048,2072) lat.
// ---------------------------------------------------------------------------
#define GSTR 36
#define GABUF (128 * GSTR)
#define GBBUF (256 * GSTR)
#define BIG_SMEM (2 * (GABUF + GBBUF) * (int)sizeof(uint32_t))   // 110592 B

__global__ void __launch_bounds__(256, 1)
gemm_big(const float* __restrict__ x, const float* __restrict__ lat,
         const int* __restrict__ idx)
{
    const int bid = blockIdx.x;
    const float* src; const __half* WT;
    float* outf = nullptr; __half* outh = nullptr;
    const float *c1, *c2;
    int nc;
    bool media;
    if (bid < 2048) {
        const int b = bid >> 8, rr = (bid >> 2) & 63, cc = bid & 3;
        const int rowBase = rr * 128;
        if (rowBase >= idx[b] * 256) return;
        src  = x + ((size_t)b * NMEDIA + rowBase) * 512;
        WT   = g_Wmed + (size_t)(cc * 256) * 512;
        outh = g_kvmed + ((size_t)b * NMEDIA + rowBase) * 1024 + cc * 256;
        c1 = g_c1med + cc * 256; c2 = g_c2med + cc * 256;
        nc = 1024; media = true;
    } else {
        const int l = bid - 2048;
        const int rr = l / 6, cc = l % 6;
        src  = lat + (size_t)(rr * 128) * 512;
        WT   = g_Wlat + (size_t)(cc * 256) * 512;
        outf = g_latproj + (size_t)(rr * 128) * 1536 + cc * 256;
        c1 = g_c1lat + cc * 256; c2 = g_c2lat + cc * 256;
        nc = 1536; media = false;
    }

    extern __shared__ uint32_t dyn[];
    uint32_t* As = dyn;                  // [2][GABUF]
    uint32_t* Bs = dyn + 2 * GABUF;      // [2][GBBUF]
    __shared__ float2 st[128];

    const int tid = threadIdx.x;
    const int ar = tid >> 4;
    const int ak = (tid & 15) * 4;
    const int aw = (tid & 15) * 2;

    float4 rv[8];
    float sm[8] = {0.f, 0.f, 0.f, 0.f, 0.f, 0.f, 0.f, 0.f};
    float sq[8] = {0.f, 0.f, 0.f, 0.f, 0.f, 0.f, 0.f, 0.f};

    auto lda = [&](int k0) {
        #pragma unroll
        for (int u = 0; u < 8; ++u)
            rv[u] = *(const float4*)(src + (size_t)(ar + 16 * u) * 512 + k0 + ak);
    };
    auto sta = [&](int buf) {
        #pragma unroll
        for (int u = 0; u < 8; ++u) {
            float4 v = rv[u];
            sm[u] += v.x + v.y + v.z + v.w;
            sq[u] = fmaf(v.x, v.x, sq[u]); sq[u] = fmaf(v.y, v.y, sq[u]);
            sq[u] = fmaf(v.z, v.z, sq[u]); sq[u] = fmaf(v.w, v.w, sq[u]);
            uint2 t;
            t.x = pack_h2(v.x, v.y);
            t.y = pack_h2(v.z, v.w);
            *(uint2*)&As[buf * GABUF + (ar + 16 * u) * GSTR + aw] = t;
        }
    };
    auto cpb = [&](int k0, int buf) {
        #pragma unroll
        for (int u = 0; u < 8; ++u) {
            int e = tid + u * 256;
            int row = e >> 3, seg = e & 7;
            cp16(&Bs[buf * GBBUF + row * GSTR + seg * 4],
                 WT + (size_t)row * 512 + k0 + seg * 8);
        }
        CP_COMMIT();
    };

    const int warp = tid >> 5, lane = tid & 31;
    const int wm = warp >> 2, wn = warp & 3;
    const int qr = lane >> 2, qc = lane & 3;

    float acc[4][8][4];
    #pragma unroll
    for (int i = 0; i < 4; ++i)
        #pragma unroll
        for (int j = 0; j < 8; ++j)
            #pragma unroll
            for (int r = 0; r < 4; ++r) acc[i][j][r] = 0.f;

    lda(0); sta(0); cpb(0, 0);

    for (int kc = 0; kc < 8; ++kc) {
        const int buf = kc & 1;
        CP_WAIT0();
        __syncthreads();

        const bool nxt = (kc < 7);
        if (nxt) { lda((kc + 1) * 64); cpb((kc + 1) * 64, buf ^ 1); }

        const uint32_t* Ab = As + buf * GABUF;
        const uint32_t* Bb = Bs + buf * GBBUF;
        #pragma unroll
        for (int ks = 0; ks < 4; ++ks) {
            uint32_t a[4][4], bb[8][2];
            #pragma unroll
            for (int i = 0; i < 4; ++i) {
                int r0 = wm * 64 + i * 16 + qr;
                a[i][0] = Ab[(r0    ) * GSTR + ks * 8 + qc    ];
                a[i][1] = Ab[(r0 + 8) * GSTR + ks * 8 + qc    ];
                a[i][2] = Ab[(r0    ) * GSTR + ks * 8 + qc + 4];
                a[i][3] = Ab[(r0 + 8) * GSTR + ks * 8 + qc + 4];
            }
            #pragma unroll
            for (int j = 0; j < 8; ++j) {
                int cb = wn * 64 + j * 8 + qr;
                bb[j][0] = Bb[cb * GSTR + ks * 8 + qc    ];
                bb[j][1] = Bb[cb * GSTR + ks * 8 + qc + 4];
            }
            #pragma unroll
            for (int i = 0; i < 4; ++i)
                #pragma unroll
                for (int j = 0; j < 8; ++j)
                    mma_f16(acc[i][j], a[i], bb[j]);
        }

        if (nxt) sta(buf ^ 1);
    }

    // ---- LN stats reduce (16-lane groups share rows) ----
    #pragma unroll
    for (int u = 0; u < 8; ++u) {
        #pragma unroll
        for (int o = 1; o < 16; o <<= 1) {
            sm[u] += __shfl_xor_sync(0xffffffffu, sm[u], o);
            sq[u] += __shfl_xor_sync(0xffffffffu, sq[u], o);
        }
    }
    if ((tid & 15) == 0) {
        #pragma unroll
        for (int u = 0; u < 8; ++u) {
            float mu  = sm[u] * (1.f / 512.f);
            float var = fmaf(-mu, mu, sq[u] * (1.f / 512.f));
            st[ar + 16 * u] = make_float2(mu, rsqrtf(var + 1e-5f));
        }
    }
    __syncthreads();

    // ---- epilogue: out = rs*acc - rs*mu*c1 + c2 ----
    #pragma unroll
    for (int i = 0; i < 4; ++i) {
        int r0 = wm * 64 + i * 16 + qr;
        float2 s0 = st[r0], s1 = st[r0 + 8];
        float rs0 = s0.y, t0 = s0.y * s0.x;
        float rs1 = s1.y, t1 = s1.y * s1.x;
        #pragma unroll
        for (int j = 0; j < 8; ++j) {
            int col = wn * 64 + j * 8 + qc * 2;
            float2 c1v = *(const float2*)(c1 + col);
            float2 c2v = *(const float2*)(c2 + col);
            float2 o0, o1;
            o0.x = fmaf(acc[i][j][0], rs0, fmaf(-t0, c1v.x, c2v.x));
            o0.y = fmaf(acc[i][j][1], rs0, fmaf(-t0, c1v.y, c2v.y));
            o1.x = fmaf(acc[i][j][2], rs1, fmaf(-t1, c1v.x, c2v.x));
            o1.y = fmaf(acc[i][j][3], rs1, fmaf(-t1, c1v.y, c2v.y));
            if (media) {
                *(__half2*)(outh + (size_t)(r0    ) * 1024 + col) = __floats2half2_rn(o0.x, o0.y);
                *(__half2*)(outh + (size_t)(r0 + 8) * 1024 + col) = __floats2half2_rn(o1.x, o1.y);
            } else {
                *(float2*)(outf + (size_t)(r0    ) * nc + col) = o0;
                *(float2*)(outf + (size_t)(r0 + 8) * nc + col) = o1;
            }
        }
    }
}

// ---------------------------------------------------------------------------
// Output projection GEMM, fp16 (R12-passing).
// ---------------------------------------------------------------------------
#define NSTR 20
#define OBUF (128 * NSTR)
#define OUT_SMEM (4 * OBUF * (int)sizeof(uint32_t))

__global__ void __launch_bounds__(256, 2)
gemm_out(const float* __restrict__ src, const float* __restrict__ bias,
         float* __restrict__ out)
{
    const int rowBase = (blockIdx.x >> 2) * 128;
    const int colBase = (blockIdx.x & 3) * 128;
    const float* srcB = src + (size_t)rowBase * 512;
    float* outB = out + (size_t)rowBase * 512;

    extern __shared__ uint32_t dyn2[];
    uint32_t* As = dyn2;
    uint32_t* Bs = dyn2 + 2 * OBUF;

    const int tid = threadIdx.x;
    const int am = tid >> 3, akq = (tid & 7) * 4;
    const int aw = (tid & 7) * 2;
    float4 rv[4];

    auto lda = [&](int k0) {
        #pragma unroll
        for (int u = 0; u < 4; ++u)
            rv[u] = *(const float4*)(srcB + (size_t)(am + 32 * u) * 512 + k0 + akq);
    };
    auto sta = [&](int buf) {
        #pragma unroll
        for (int u = 0; u < 4; ++u) {
            float4 v = rv[u];
            uint2 t;
            t.x = pack_h2(v.x, v.y);
            t.y = pack_h2(v.z, v.w);
            *(uint2*)&As[buf * OBUF + (am + 32 * u) * NSTR + aw] = t;
        }
    };
    auto cpb = [&](int k0, int buf) {
        #pragma unroll
        for (int u = 0; u < 2; ++u) {
            int e = tid + u * 256;
            int row = e >> 2, seg = e & 3;
            cp16(&Bs[buf * OBUF + row * NSTR + seg * 4],
                 g_WoT + (size_t)(colBase + row) * 512 + k0 + seg * 8);
        }
        CP_COMMIT();
    };

    const int warp = tid >> 5, lane = tid & 31;
    const int wm = warp >> 2, wn = warp & 3;
    const int qr = lane >> 2, qc = lane & 3;

    float acc[4][4][4];
    #pragma unroll
    for (int i = 0; i < 4; ++i)
        #pragma unroll
        for (int j = 0; j < 4; ++j)
            #pragma unroll
            for (int r = 0; r < 4; ++r) acc[i][j][r] = 0.f;

    lda(0); sta(0); cpb(0, 0);

    for (int kc = 0; kc < 16; ++kc) {
        const int buf = kc & 1;
        CP_WAIT0();
        __syncthreads();
        const bool nxt = (kc < 15);
        if (nxt) { lda((kc + 1) * 32); cpb((kc + 1) * 32, buf ^ 1); }

        const uint32_t* Ab = As + buf * OBUF;
        const uint32_t* Bb = Bs + buf * OBUF;
        #pragma unroll
        for (int ks = 0; ks < 2; ++ks) {
            uint32_t a[4][4], bb[4][2];
            #pragma unroll
            for (int i = 0; i < 4; ++i) {
                int r0 = wm * 64 + i * 16 + qr;
                a[i][0] = Ab[(r0    ) * NSTR + ks * 8 + qc    ];
                a[i][1] = Ab[(r0 + 8) * NSTR + ks * 8 + qc    ];
                a[i][2] = Ab[(r0    ) * NSTR + ks * 8 + qc + 4];
                a[i][3] = Ab[(r0 + 8) * NSTR + ks * 8 + qc + 4];
            }
            #pragma unroll
            for (int j = 0; j < 4; ++j) {
                int cb = wn * 32 + j * 8 + qr;
                bb[j][0] = Bb[cb * NSTR + ks * 8 + qc    ];
                bb[j][1] = Bb[cb * NSTR + ks * 8 + qc + 4];
            }
            #pragma unroll
            for (int i = 0; i < 4; ++i)
                #pragma unroll
                for (int j = 0; j < 4; ++j)
                    mma_f16(acc[i][j], a[i], bb[j]);
        }
        if (nxt) sta(buf ^ 1);
    }

    #pragma unroll
    for (int i = 0; i < 4; ++i) {
        int r0 = wm * 64 + i * 16 + qr;
        #pragma unroll
        for (int j = 0; j < 4; ++j) {
            int col = colBase + wn * 32 + j * 8 + qc * 2;
            float2 bi = *(const float2*)(bias + col);
            *(float2*)(outB + (size_t)(r0    ) * 512 + col) =
                make_float2(acc[i][j][0] + bi.x, acc[i][j][1] + bi.y);
            *(float2*)(outB + (size_t)(r0 + 8) * 512 + col) =
                make_float2(acc[i][j][2] + bi.x, acc[i][j][3] + bi.y);
        }
    }
}

// ---------------------------------------------------------------------------
// fp16 split-KV flash attention, merged 512-token windows (8 chunks) + latent.
// grid = (17, HEADS, BATCH). Window w processes nch = clamp(vis*4 - w*8, 0, 8)
// 64-key chunks (visibility is 256-aligned = 4-chunk-aligned). Pipelined
// double-buffered K/V, one __syncthreads per chunk (R12-validated structure).
// ---------------------------------------------------------------------------
#define ASTR 36
#define ABLK (64 * ASTR)
#define ATTN_SMEM (6 * ABLK * (int)sizeof(uint32_t))   // 55296 B

__global__ void __launch_bounds__(128)
attn_split_f16(const float* __restrict__ latproj, const int* __restrict__ indices)
{
    const int b = blockIdx.z, h = blockIdx.y, s = blockIdx.x;
    const int vis = indices[b];
    const bool is_lat = (s == 16);
    int nch;
    if (is_lat) {
        nch = 1;
    } else {
        nch = vis * 4 - s * 8;
        if (nch <= 0) return;
        if (nch > 8) nch = 8;
    }

    extern __shared__ uint32_t smw[];
    uint32_t* Qs = smw;                  // [64][36]
    uint32_t* Ps = Qs + ABLK;            // [64][36]
    uint32_t* Ks = Ps + ABLK;            // [2][64][36]
    uint32_t* Vp = Ks + 2 * ABLK;        // [2][64][36] d-major, half2 along j

    const int tid = threadIdx.x, warp = tid >> 5, lane = tid & 31;
    const int qr = lane >> 2, qc = lane & 3;
    const int r0 = warp * 16 + qr;

    // ---- load Q (fp32 -> packed fp16) ----
    #pragma unroll
    for (int it = 0; it < 4; ++it) {
        int e = tid + it * 128;
        int r = e >> 3, c8 = (e & 7) * 8;
        const float* qp = latproj + ((size_t)b * 64 + r) * 1536 + h * 64 + c8;
        float4 v0 = *(const float4*)qp;
        float4 v1 = *(const float4*)(qp + 4);
        uint4 t;
        t.x = pack_h2(v0.x, v0.y); t.y = pack_h2(v0.z, v0.w);
        t.z = pack_h2(v1.x, v1.y); t.w = pack_h2(v1.z, v1.w);
        *(uint4*)&Qs[r * ASTR + (e & 7) * 4] = t;
    }

    const __half* kvb_h = g_kvmed + ((size_t)b * NMEDIA + (size_t)s * 512) * 1024;
    const float*  kvb_f = latproj + (size_t)b * 64 * 1536;
    const int koff_h = h * 64, voff_h = 512 + h * 64;
    const int koff_f = 512 + h * 64, voff_f = 1024 + h * 64;

    uint4 kreg[4], vreg[4];
    auto loadregs = [&](int ch) {
        #pragma unroll
        for (int it = 0; it < 4; ++it) {
            int e = tid + it * 128;
            int j = e >> 3, d0 = (e & 7) * 8;
            if (is_lat) {
                const float* rp = kvb_f + (size_t)j * 1536;
                __half kh[8], vh[8];
                #pragma unroll
                for (int i = 0; i < 8; ++i) {
                    kh[i] = __float2half_rn(rp[koff_f + d0 + i]);
                    vh[i] = __float2half_rn(rp[voff_f + d0 + i]);
                }
                kreg[it] = *(const uint4*)kh;
                vreg[it] = *(const uint4*)vh;
            } else {
                const __half* rp = kvb_h + (size_t)(ch * 64 + j) * 1024;
                kreg[it] = *(const uint4*)(rp + koff_h + d0);
                vreg[it] = *(const uint4*)(rp + voff_h + d0);
            }
        }
    };
    auto storeregs = [&](int buf) {
        uint32_t* Kb = Ks + buf * ABLK;
        __half*   Vb = (__half*)(Vp + buf * ABLK);
        #pragma unroll
        for (int it = 0; it < 4; ++it) {
            int e = tid + it * 128;
            int j = e >> 3, w4 = e & 7, d0 = w4 * 8;
            *(uint4*)&Kb[j * ASTR + w4 * 4] = kreg[it];
            const __half* vh = (const __half*)&vreg[it];
            #pragma unroll
            for (int i = 0; i < 8; ++i)
                Vb[(d0 + i) * (2 * ASTR) + j] = vh[i];
        }
    };

    float m0 = -CUDART_INF_F, m1 = -CUDART_INF_F, l0 = 0.f, l1 = 0.f;
    float o[8][4];
    #pragma unroll
    for (int nf = 0; nf < 8; ++nf)
        #pragma unroll
        for (int r = 0; r < 4; ++r) o[nf][r] = 0.f;

    loadregs(0);
    storeregs(0);
    __syncthreads();

    for (int ch = 0; ch < nch; ++ch) {
        const int buf = ch & 1;
        const bool nxt = (ch + 1 < nch);
        if (nxt) loadregs(ch + 1);

        const uint32_t* Kb = Ks + buf * ABLK;
        const uint32_t* Vb = Vp + buf * ABLK;

        float sacc[8][4] = {};
        #pragma unroll
        for (int ks = 0; ks < 4; ++ks) {
            uint32_t a[4];
            a[0] = Qs[(r0    ) * ASTR + ks * 8 + qc    ];
            a[1] = Qs[(r0 + 8) * ASTR + ks * 8 + qc    ];
            a[2] = Qs[(r0    ) * ASTR + ks * 8 + qc + 4];
            a[3] = Qs[(r0 + 8) * ASTR + ks * 8 + qc + 4];
            #pragma unroll
            for (int nf = 0; nf < 8; ++nf) {
                uint32_t bb[2];
                bb[0] = Kb[(nf * 8 + qr) * ASTR + ks * 8 + qc    ];
                bb[1] = Kb[(nf * 8 + qr) * ASTR + ks * 8 + qc + 4];
                mma_f16(sacc[nf], a, bb);
            }
        }

        float rm0 = -CUDART_INF_F, rm1 = -CUDART_INF_F;
        #pragma unroll
        for (int nf = 0; nf < 8; ++nf) {
            rm0 = fmaxf(rm0, fmaxf(sacc[nf][0], sacc[nf][1]));
            rm1 = fmaxf(rm1, fmaxf(sacc[nf][2], sacc[nf][3]));
        }
        rm0 = fmaxf(rm0, __shfl_xor_sync(0xffffffffu, rm0, 1));
        rm0 = fmaxf(rm0, __shfl_xor_sync(0xffffffffu, rm0, 2));
        rm1 = fmaxf(rm1, __shfl_xor_sync(0xffffffffu, rm1, 1));
        rm1 = fmaxf(rm1, __shfl_xor_sync(0xffffffffu, rm1, 2));
        float mn0 = fmaxf(m0, rm0), mn1 = fmaxf(m1, rm1);
        float cc0 = __expf(m0 - mn0), cc1 = __expf(m1 - mn1);
        float s0 = 0.f, s1 = 0.f;
        #pragma unroll
        for (int nf = 0; nf < 8; ++nf) {
            float p00 = __expf(sacc[nf][0] - mn0);
            float p01 = __expf(sacc[nf][1] - mn0);
            float p10 = __expf(sacc[nf][2] - mn1);
            float p11 = __expf(sacc[nf][3] - mn1);
            s0 += p00 + p01; s1 += p10 + p11;
            Ps[(r0    ) * ASTR + nf * 4 + qc] = pack_h2(p00, p01);
            Ps[(r0 + 8) * ASTR + nf * 4 + qc] = pack_h2(p10, p11);
            o[nf][0] *= cc0; o[nf][1] *= cc0;
            o[nf][2] *= cc1; o[nf][3] *= cc1;
        }
        s0 += __shfl_xor_sync(0xffffffffu, s0, 1);
        s0 += __shfl_xor_sync(0xffffffffu, s0, 2);
        s1 += __shfl_xor_sync(0xffffffffu, s1, 1);
        s1 += __shfl_xor_sync(0xffffffffu, s1, 2);
        m0 = mn0; m1 = mn1;
        l0 = fmaf(l0, cc0, s0);
        l1 = fmaf(l1, cc1, s1);
        __syncwarp();

        #pragma unroll
        for (int ks = 0; ks < 4; ++ks) {
            uint32_t a[4];
            a[0] = Ps[(r0    ) * ASTR + ks * 8 + qc    ];
            a[1] = Ps[(r0 + 8) * ASTR + ks * 8 + qc    ];
            a[2] = Ps[(r0    ) * ASTR + ks * 8 + qc + 4];
            a[3] = Ps[(r0 + 8) * ASTR + ks * 8 + qc + 4];
            #pragma unroll
            for (int nf = 0; nf < 8; ++nf) {
                uint32_t bb[2];
                bb[0] = Vb[(nf * 8 + qr) * ASTR + ks * 8 + qc    ];
                bb[1] = Vb[(nf * 8 + qr) * ASTR + ks * 8 + qc + 4];
                mma_f16(o[nf], a, bb);
            }
        }

        if (nxt) {
            storeregs(buf ^ 1);
            __syncthreads();
        }
    }

    // ---- write partials ----
    const size_t pbase = ((size_t)(b * HEADS + h)) * NSP + s;
    float* op = g_opart + pbase * 4096;
    #pragma unroll
    for (int nf = 0; nf < 8; ++nf) {
        *(float2*)&op[(r0    ) * 64 + nf * 8 + qc * 2] = make_float2(o[nf][0], o[nf][1]);
        *(float2*)&op[(r0 + 8) * 64 + nf * 8 + qc * 2] = make_float2(o[nf][2], o[nf][3]);
    }
    if (qc == 0) {
        g_mpart[pbase * 64 + r0    ] = m0;
        g_mpart[pbase * 64 + r0 + 8] = m1;
        g_lpart[pbase * 64 + r0    ] = l0;
        g_lpart[pbase * 64 + r0 + 8] = l1;
    }
}

// ---------------------------------------------------------------------------
// Combine window partials -> attn_out. Media windows w < ceil(vis/2),
// latent at slot 16.
// ---------------------------------------------------------------------------
__global__ void __launch_bounds__(256)
attn_combine(const int* __restrict__ indices, float* __restrict__ attn_out)
{
    const int bh = blockIdx.x;
    const int b = bh >> 3, h = bh & 7;
    const int visw = (indices[b] + 1) >> 1;     // media windows with work
    const int warp = threadIdx.x >> 5, lane = threadIdx.x & 31;
    const int i = blockIdx.y * 8 + warp;

    __shared__ float ws[8][17];
    __shared__ float linv[8];

    const size_t base = (size_t)bh * NSP;

    float m    = (lane < visw) ? g_mpart[(base + lane) * 64 + i] : -CUDART_INF_F;
    float mlat = g_mpart[(base + 16) * 64 + i];
    float mm = fmaxf(m, mlat);
    #pragma unroll
    for (int o = 16; o > 0; o >>= 1)
        mm = fmaxf(mm, __shfl_xor_sync(0xffffffffu, mm, o));

    float w  = (lane < visw) ? __expf(m - mm) : 0.f;
    float wl = __expf(mlat - mm);
    float l  = (lane < visw) ? g_lpart[(base + lane) * 64 + i] * w : 0.f;
    #pragma unroll
    for (int o = 16; o > 0; o >>= 1)
        l += __shfl_xor_sync(0xffffffffu, l, o);
    float ll = g_lpart[(base + 16) * 64 + i] * wl;

    if (lane < 16) ws[warp][lane] = w;
    if (lane == 0) {
        ws[warp][16] = wl;
        linv[warp] = 1.f / (l + ll);
    }
    __syncwarp();

    const int d = lane * 2;
    float2 v = *(const float2*)(g_opart + (base + 16) * 4096 + i * 64 + d);
    float a0 = v.x * ws[warp][16];
    float a1 = v.y * ws[warp][16];
    for (int s = 0; s < visw; ++s) {
        float wv = ws[warp][s];
        float2 u = *(const float2*)(g_opart + (base + s) * 4096 + i * 64 + d);
        a0 = fmaf(u.x, wv, a0);
        a1 = fmaf(u.y, wv, a1);
    }
    float li = linv[warp];
    *(float2*)(attn_out + ((size_t)b * 64 + i) * 512 + h * 64 + d) =
        make_float2(a0 * li, a1 * li);
}

// ---------------------------------------------------------------------------
// Launch
// ---------------------------------------------------------------------------
extern "C" void kernel_launch(void* const* d_in, const int* in_sizes, int n_in,
                              void* d_out, int out_size)
{
    (void)in_sizes; (void)n_in; (void)out_size;
    const float* x    = (const float*)d_in[0];
    const float* lat  = (const float*)d_in[1];
    const int*   idx  = (const int*)  d_in[2];
    const float* g_m  = (const float*)d_in[3];
    const float* b_m  = (const float*)d_in[4];
    const float* g_l  = (const float*)d_in[5];
    const float* b_l  = (const float*)d_in[6];
    const float* Wq   = (const float*)d_in[7];
    const float* bq   = (const float*)d_in[8];
    const float* Wkv  = (const float*)d_in[9];
    const float* bkv  = (const float*)d_in[10];
    const float* Wo   = (const float*)d_in[11];
    const float* bo   = (const float*)d_in[12];
    float* out = (float*)d_out;

    void *plp, *pattno;
    cudaGetSymbolAddress(&plp,    g_latproj);
    cudaGetSymbolAddress(&pattno, g_attno);

    cudaFuncSetAttribute(gemm_big,
                         cudaFuncAttributeMaxDynamicSharedMemorySize, BIG_SMEM);
    cudaFuncSetAttribute(gemm_out,
                         cudaFuncAttributeMaxDynamicSharedMemorySize, OUT_SMEM);
    cudaFuncSetAttribute(attn_split_f16,
                         cudaFuncAttributeMaxDynamicSharedMemorySize, ATTN_SMEM);

    // weight + column-vector prep
    prep_w<<<dim3(16, 8, 4), 256>>>(Wq, Wkv, Wo, g_l, g_m);
    prep_c<<<40, 256>>>(Wq, Wkv, bq, bkv, b_l, b_m);

    // unified media-KV (fp16 out) + latent projections (K-chunk 64, R12)
    gemm_big<<<2072, 256, BIG_SMEM>>>(x, lat, idx);

    // attention (merged 512-token windows) + combine
    attn_split_f16<<<dim3(NSP, HEADS, BATCH), 128, ATTN_SMEM>>>(
        (const float*)plp, idx);
    attn_combine<<<dim3(64, 8), 256>>>(idx, (float*)pattno);

    // output projection
    gemm_out<<<16, 256, OUT_SMEM>>>((const float*)pattno, bo, out);
}

// round 15
// speedup vs baseline: 1.0466x; 1.0006x over previous
#include <cuda_runtime.h>
#include <cuda_fp16.h>
#include <math_constants.h>
#include <cstdint>
#include <cstddef>
#include <cstring>

// ---------------------------------------------------------------------------
// Problem constants
// ---------------------------------------------------------------------------
#define BATCH   8
#define NMEDIA  8192
#define SLAT    64
#define HEADS   8
#define NSP     17          // 16 media windows (512 tokens) + 1 latent

// ---------------------------------------------------------------------------
// Scratch (device globals)
// ---------------------------------------------------------------------------
__device__ float    g_latproj[(size_t)512 * 1536];                  // [q | k | v] fp32
__device__ __half   g_kvmed [(size_t)BATCH * NMEDIA * 1024];        // fp16 KV cache
__device__ float    g_opart [(size_t)64 * NSP * 64 * 64];
__device__ float    g_mpart [(size_t)64 * NSP * 64];
__device__ float    g_lpart [(size_t)64 * NSP * 64];
__device__ float    g_attno [(size_t)512 * 512];
__device__ __half   g_Wlat  [(size_t)1536 * 512];   // [0.125*g_l*Wq | g_l*Wkv]^T fp16
__device__ __half   g_Wmed  [(size_t)1024 * 512];   // [g_m*Wkv]^T fp16
__device__ __half   g_WoT   [(size_t)512 * 512];    // Wo^T fp16
__device__ float    g_c1lat[1536], g_c2lat[1536];
__device__ float    g_c1med[1024], g_c2med[1024];

// ---------------------------------------------------------------------------
// Helpers
// ---------------------------------------------------------------------------
__device__ __forceinline__ uint32_t pack_h2(float lo, float hi) {
    __half2 h = __floats2half2_rn(lo, hi);
    return *(uint32_t*)&h;
}

__device__ __forceinline__ void mma_f16(float* c, const uint32_t* a, const uint32_t* b) {
    asm volatile(
        "mma.sync.aligned.m16n8k16.row.col.f32.f16.f16.f32 "
        "{%0,%1,%2,%3},{%4,%5,%6,%7},{%8,%9},{%0,%1,%2,%3};"
        : "+f"(c[0]), "+f"(c[1]), "+f"(c[2]), "+f"(c[3])
        : "r"(a[0]), "r"(a[1]), "r"(a[2]), "r"(a[3]), "r"(b[0]), "r"(b[1]));
}

__device__ __forceinline__ void cp16(void* smem, const void* gmem) {
    uint32_t a = (uint32_t)__cvta_generic_to_shared(smem);
    asm volatile("cp.async.cg.shared.global [%0], [%1], 16;" :: "r"(a), "l"(gmem));
}
#define CP_COMMIT() asm volatile("cp.async.commit_group;")
#define CP_WAIT0()  asm volatile("cp.async.wait_group 0;" ::: "memory")

// ---------------------------------------------------------------------------
// Weight prep (R14-passing): transpose + g-fold + scale-fold + fp16 convert.
// ---------------------------------------------------------------------------
__global__ void __launch_bounds__(256)
prep_w(const float* __restrict__ Wq, const float* __restrict__ Wkv,
       const float* __restrict__ Wo, const float* __restrict__ gl,
       const float* __restrict__ gm)
{
    const float* W; __half* WT; const float* gv; int nc; float scale = 1.f;
    switch (blockIdx.z) {
        case 0:  W = Wq;  WT = g_Wlat;             gv = gl;      nc = 512;  scale = 0.125f; break;
        case 1:  W = Wkv; WT = g_Wlat + 512 * 512; gv = gl;      nc = 1024; break;
        case 2:  W = Wkv; WT = g_Wmed;             gv = gm;      nc = 1024; break;
        default: W = Wo;  WT = g_WoT;              gv = nullptr; nc = 512;  break;
    }
    const int c0 = blockIdx.x * 64;
    if (c0 >= nc) return;
    const int k0 = blockIdx.y * 64;
    const int tid = threadIdx.x;

    __shared__ float ts[64][65];
    #pragma unroll
    for (int it = 0; it < 16; ++it) {
        int e = tid + it * 256;
        int k = e >> 6, c = e & 63;
        float gk = gv ? gv[k0 + k] * scale : scale;
        ts[k][c] = W[(size_t)(k0 + k) * nc + c0 + c] * gk;
    }
    __syncthreads();
    #pragma unroll
    for (int it = 0; it < 16; ++it) {
        int e = tid + it * 256;
        int c = e >> 6, k = e & 63;
        WT[(size_t)(c0 + c) * 512 + (k0 + k)] = __float2half_rn(ts[k][c]);
    }
}

// ---------------------------------------------------------------------------
// Column-vector prep (R14-passing).
// ---------------------------------------------------------------------------
__global__ void __launch_bounds__(256)
prep_c(const float* __restrict__ Wq, const float* __restrict__ Wkv,
       const float* __restrict__ bq, const float* __restrict__ bkv,
       const float* __restrict__ bl, const float* __restrict__ bm)
{
    const int bx = blockIdx.x;
    const float *W, *bv, *bias;
    const __half* WT;
    float *c1o, *c2o;
    int nc, srcCol, colBase;
    float scale = 1.f;

    if (bx < 24) {
        colBase = bx * 64;
        if (colBase < 512) { W = Wq;  nc = 512;  bias = bq;  srcCol = colBase;       scale = 0.125f; }
        else               { W = Wkv; nc = 1024; bias = bkv; srcCol = colBase - 512; }
        bv = bl; WT = g_Wlat; c1o = g_c1lat; c2o = g_c2lat;
    } else {
        colBase = (bx - 24) * 64;
        W = Wkv; nc = 1024; bias = bkv; srcCol = colBase;
        bv = bm; WT = g_Wmed; c1o = g_c1med; c2o = g_c2med;
    }

    const int tid = threadIdx.x;
    {
        const int c = tid & 63, kq = tid >> 6;
        float part = 0.f;
        for (int k = kq; k < 512; k += 4)
            part = fmaf(bv[k], W[(size_t)k * nc + srcCol + c], part);
        __shared__ float red[4][64];
        red[kq][c] = part;
        __syncthreads();
        if (tid < 64) {
            float s = red[0][tid] + red[1][tid] + red[2][tid] + red[3][tid];
            c2o[colBase + tid] = (s + bias[srcCol + tid]) * scale;
        }
    }
    {
        const int warp = tid >> 5, lane = tid & 31;
        #pragma unroll
        for (int cc = 0; cc < 8; ++cc) {
            int col = colBase + warp * 8 + cc;
            const __half* p = WT + (size_t)col * 512;
            float s = 0.f;
            #pragma unroll
            for (int u = 0; u < 16; ++u)
                s += __half2float(p[lane + 32 * u]);
            #pragma unroll
            for (int o = 16; o > 0; o >>= 1)
                s += __shfl_xor_sync(0xffffffffu, s, o);
            if (lane == 0) c1o[col] = s;
        }
    }
}

// ---------------------------------------------------------------------------
// Unified big GEMM (R14-passing, KC=64): 128x256 tile, 256 threads,
// 8 chunks, double-buffered (A register prefetch + LN stats, B cp.async),
// stride-36 smem rows. Grid: [0,2048) media (mask-skipped), [2048,2072) lat.
// ---------------------------------------------------------------------------
#define GSTR 36
#define GABUF (128 * GSTR)
#define GBBUF (256 * GSTR)
#define BIG_SMEM (2 * (GABUF + GBBUF) * (int)sizeof(uint32_t))   // 110592 B

__global__ void __launch_bounds__(256, 1)
gemm_big(const float* __restrict__ x, const float* __restrict__ lat,
         const int* __restrict__ idx)
{
    const int bid = blockIdx.x;
    const float* src; const __half* WT;
    float* outf = nullptr; __half* outh = nullptr;
    const float *c1, *c2;
    int nc;
    bool media;
    if (bid < 2048) {
        const int b = bid >> 8, rr = (bid >> 2) & 63, cc = bid & 3;
        const int rowBase = rr * 128;
        if (rowBase >= idx[b] * 256) return;
        src  = x + ((size_t)b * NMEDIA + rowBase) * 512;
        WT   = g_Wmed + (size_t)(cc * 256) * 512;
        outh = g_kvmed + ((size_t)b * NMEDIA + rowBase) * 1024 + cc * 256;
        c1 = g_c1med + cc * 256; c2 = g_c2med + cc * 256;
        nc = 1024; media = true;
    } else {
        const int l = bid - 2048;
        const int rr = l / 6, cc = l % 6;
        src  = lat + (size_t)(rr * 128) * 512;
        WT   = g_Wlat + (size_t)(cc * 256) * 512;
        outf = g_latproj + (size_t)(rr * 128) * 1536 + cc * 256;
        c1 = g_c1lat + cc * 256; c2 = g_c2lat + cc * 256;
        nc = 1536; media = false;
    }

    extern __shared__ uint32_t dyn[];
    uint32_t* As = dyn;                  // [2][GABUF]
    uint32_t* Bs = dyn + 2 * GABUF;      // [2][GBBUF]
    __shared__ float2 st[128];

    const int tid = threadIdx.x;
    const int ar = tid >> 4;
    const int ak = (tid & 15) * 4;
    const int aw = (tid & 15) * 2;

    float4 rv[8];
    float sm[8] = {0.f, 0.f, 0.f, 0.f, 0.f, 0.f, 0.f, 0.f};
    float sq[8] = {0.f, 0.f, 0.f, 0.f, 0.f, 0.f, 0.f, 0.f};

    auto lda = [&](int k0) {
        #pragma unroll
        for (int u = 0; u < 8; ++u)
            rv[u] = *(const float4*)(src + (size_t)(ar + 16 * u) * 512 + k0 + ak);
    };
    auto sta = [&](int buf) {
        #pragma unroll
        for (int u = 0; u < 8; ++u) {
            float4 v = rv[u];
            sm[u] += v.x + v.y + v.z + v.w;
            sq[u] = fmaf(v.x, v.x, sq[u]); sq[u] = fmaf(v.y, v.y, sq[u]);
            sq[u] = fmaf(v.z, v.z, sq[u]); sq[u] = fmaf(v.w, v.w, sq[u]);
            uint2 t;
            t.x = pack_h2(v.x, v.y);
            t.y = pack_h2(v.z, v.w);
            *(uint2*)&As[buf * GABUF + (ar + 16 * u) * GSTR + aw] = t;
        }
    };
    auto cpb = [&](int k0, int buf) {
        #pragma unroll
        for (int u = 0; u < 8; ++u) {
            int e = tid + u * 256;
            int row = e >> 3, seg = e & 7;
            cp16(&Bs[buf * GBBUF + row * GSTR + seg * 4],
                 WT + (size_t)row * 512 + k0 + seg * 8);
        }
        CP_COMMIT();
    };

    const int warp = tid >> 5, lane = tid & 31;
    const int wm = warp >> 2, wn = warp & 3;
    const int qr = lane >> 2, qc = lane & 3;

    float acc[4][8][4];
    #pragma unroll
    for (int i = 0; i < 4; ++i)
        #pragma unroll
        for (int j = 0; j < 8; ++j)
            #pragma unroll
            for (int r = 0; r < 4; ++r) acc[i][j][r] = 0.f;

    lda(0); sta(0); cpb(0, 0);

    for (int kc = 0; kc < 8; ++kc) {
        const int buf = kc & 1;
        CP_WAIT0();
        __syncthreads();

        const bool nxt = (kc < 7);
        if (nxt) { lda((kc + 1) * 64); cpb((kc + 1) * 64, buf ^ 1); }

        const uint32_t* Ab = As + buf * GABUF;
        const uint32_t* Bb = Bs + buf * GBBUF;
        #pragma unroll
        for (int ks = 0; ks < 4; ++ks) {
            uint32_t a[4][4], bb[8][2];
            #pragma unroll
            for (int i = 0; i < 4; ++i) {
                int r0 = wm * 64 + i * 16 + qr;
                a[i][0] = Ab[(r0    ) * GSTR + ks * 8 + qc    ];
                a[i][1] = Ab[(r0 + 8) * GSTR + ks * 8 + qc    ];
                a[i][2] = Ab[(r0    ) * GSTR + ks * 8 + qc + 4];
                a[i][3] = Ab[(r0 + 8) * GSTR + ks * 8 + qc + 4];
            }
            #pragma unroll
            for (int j = 0; j < 8; ++j) {
                int cb = wn * 64 + j * 8 + qr;
                bb[j][0] = Bb[cb * GSTR + ks * 8 + qc    ];
                bb[j][1] = Bb[cb * GSTR + ks * 8 + qc + 4];
            }
            #pragma unroll
            for (int i = 0; i < 4; ++i)
                #pragma unroll
                for (int j = 0; j < 8; ++j)
                    mma_f16(acc[i][j], a[i], bb[j]);
        }

        if (nxt) sta(buf ^ 1);
    }

    // ---- LN stats reduce (16-lane groups share rows) ----
    #pragma unroll
    for (int u = 0; u < 8; ++u) {
        #pragma unroll
        for (int o = 1; o < 16; o <<= 1) {
            sm[u] += __shfl_xor_sync(0xffffffffu, sm[u], o);
            sq[u] += __shfl_xor_sync(0xffffffffu, sq[u], o);
        }
    }
    if ((tid & 15) == 0) {
        #pragma unroll
        for (int u = 0; u < 8; ++u) {
            float mu  = sm[u] * (1.f / 512.f);
            float var = fmaf(-mu, mu, sq[u] * (1.f / 512.f));
            st[ar + 16 * u] = make_float2(mu, rsqrtf(var + 1e-5f));
        }
    }
    __syncthreads();

    // ---- epilogue: out = rs*acc - rs*mu*c1 + c2 ----
    #pragma unroll
    for (int i = 0; i < 4; ++i) {
        int r0 = wm * 64 + i * 16 + qr;
        float2 s0 = st[r0], s1 = st[r0 + 8];
        float rs0 = s0.y, t0 = s0.y * s0.x;
        float rs1 = s1.y, t1 = s1.y * s1.x;
        #pragma unroll
        for (int j = 0; j < 8; ++j) {
            int col = wn * 64 + j * 8 + qc * 2;
            float2 c1v = *(const float2*)(c1 + col);
            float2 c2v = *(const float2*)(c2 + col);
            float2 o0, o1;
            o0.x = fmaf(acc[i][j][0], rs0, fmaf(-t0, c1v.x, c2v.x));
            o0.y = fmaf(acc[i][j][1], rs0, fmaf(-t0, c1v.y, c2v.y));
            o1.x = fmaf(acc[i][j][2], rs1, fmaf(-t1, c1v.x, c2v.x));
            o1.y = fmaf(acc[i][j][3], rs1, fmaf(-t1, c1v.y, c2v.y));
            if (media) {
                *(__half2*)(outh + (size_t)(r0    ) * 1024 + col) = __floats2half2_rn(o0.x, o0.y);
                *(__half2*)(outh + (size_t)(r0 + 8) * 1024 + col) = __floats2half2_rn(o1.x, o1.y);
            } else {
                *(float2*)(outf + (size_t)(r0    ) * nc + col) = o0;
                *(float2*)(outf + (size_t)(r0 + 8) * nc + col) = o1;
            }
        }
    }
}

// ---------------------------------------------------------------------------
// Output projection GEMM, fp16 (R14-passing).
// ---------------------------------------------------------------------------
#define NSTR 20
#define OBUF (128 * NSTR)
#define OUT_SMEM (4 * OBUF * (int)sizeof(uint32_t))

__global__ void __launch_bounds__(256, 2)
gemm_out(const float* __restrict__ src, const float* __restrict__ bias,
         float* __restrict__ out)
{
    const int rowBase = (blockIdx.x >> 2) * 128;
    const int colBase = (blockIdx.x & 3) * 128;
    const float* srcB = src + (size_t)rowBase * 512;
    float* outB = out + (size_t)rowBase * 512;

    extern __shared__ uint32_t dyn2[];
    uint32_t* As = dyn2;
    uint32_t* Bs = dyn2 + 2 * OBUF;

    const int tid = threadIdx.x;
    const int am = tid >> 3, akq = (tid & 7) * 4;
    const int aw = (tid & 7) * 2;
    float4 rv[4];

    auto lda = [&](int k0) {
        #pragma unroll
        for (int u = 0; u < 4; ++u)
            rv[u] = *(const float4*)(srcB + (size_t)(am + 32 * u) * 512 + k0 + akq);
    };
    auto sta = [&](int buf) {
        #pragma unroll
        for (int u = 0; u < 4; ++u) {
            float4 v = rv[u];
            uint2 t;
            t.x = pack_h2(v.x, v.y);
            t.y = pack_h2(v.z, v.w);
            *(uint2*)&As[buf * OBUF + (am + 32 * u) * NSTR + aw] = t;
        }
    };
    auto cpb = [&](int k0, int buf) {
        #pragma unroll
        for (int u = 0; u < 2; ++u) {
            int e = tid + u * 256;
            int row = e >> 2, seg = e & 3;
            cp16(&Bs[buf * OBUF + row * NSTR + seg * 4],
                 g_WoT + (size_t)(colBase + row) * 512 + k0 + seg * 8);
        }
        CP_COMMIT();
    };

    const int warp = tid >> 5, lane = tid & 31;
    const int wm = warp >> 2, wn = warp & 3;
    const int qr = lane >> 2, qc = lane & 3;

    float acc[4][4][4];
    #pragma unroll
    for (int i = 0; i < 4; ++i)
        #pragma unroll
        for (int j = 0; j < 4; ++j)
            #pragma unroll
            for (int r = 0; r < 4; ++r) acc[i][j][r] = 0.f;

    lda(0); sta(0); cpb(0, 0);

    for (int kc = 0; kc < 16; ++kc) {
        const int buf = kc & 1;
        CP_WAIT0();
        __syncthreads();
        const bool nxt = (kc < 15);
        if (nxt) { lda((kc + 1) * 32); cpb((kc + 1) * 32, buf ^ 1); }

        const uint32_t* Ab = As + buf * OBUF;
        const uint32_t* Bb = Bs + buf * OBUF;
        #pragma unroll
        for (int ks = 0; ks < 2; ++ks) {
            uint32_t a[4][4], bb[4][2];
            #pragma unroll
            for (int i = 0; i < 4; ++i) {
                int r0 = wm * 64 + i * 16 + qr;
                a[i][0] = Ab[(r0    ) * NSTR + ks * 8 + qc    ];
                a[i][1] = Ab[(r0 + 8) * NSTR + ks * 8 + qc    ];
                a[i][2] = Ab[(r0    ) * NSTR + ks * 8 + qc + 4];
                a[i][3] = Ab[(r0 + 8) * NSTR + ks * 8 + qc + 4];
            }
            #pragma unroll
            for (int j = 0; j < 4; ++j) {
                int cb = wn * 32 + j * 8 + qr;
                bb[j][0] = Bb[cb * NSTR + ks * 8 + qc    ];
                bb[j][1] = Bb[cb * NSTR + ks * 8 + qc + 4];
            }
            #pragma unroll
            for (int i = 0; i < 4; ++i)
                #pragma unroll
                for (int j = 0; j < 4; ++j)
                    mma_f16(acc[i][j], a[i], bb[j]);
        }
        if (nxt) sta(buf ^ 1);
    }

    #pragma unroll
    for (int i = 0; i < 4; ++i) {
        int r0 = wm * 64 + i * 16 + qr;
        #pragma unroll
        for (int j = 0; j < 4; ++j) {
            int col = colBase + wn * 32 + j * 8 + qc * 2;
            float2 bi = *(const float2*)(bias + col);
            *(float2*)(outB + (size_t)(r0    ) * 512 + col) =
                make_float2(acc[i][j][0] + bi.x, acc[i][j][1] + bi.y);
            *(float2*)(outB + (size_t)(r0 + 8) * 512 + col) =
                make_float2(acc[i][j][2] + bi.x, acc[i][j][3] + bi.y);
        }
    }
}

// ---------------------------------------------------------------------------
// fp16 split-KV flash attention, 512-token windows + latent (R14 structure).
// K now staged via cp.async (no register roundtrip, no reformat needed);
// V register-prefetched (needs d-major transpose). One barrier per chunk.
// ---------------------------------------------------------------------------
#define ASTR 36
#define ABLK (64 * ASTR)
#define ATTN_SMEM (6 * ABLK * (int)sizeof(uint32_t))   // 55296 B

__global__ void __launch_bounds__(128)
attn_split_f16(const float* __restrict__ latproj, const int* __restrict__ indices)
{
    const int b = blockIdx.z, h = blockIdx.y, s = blockIdx.x;
    const int vis = indices[b];
    const bool is_lat = (s == 16);
    int nch;
    if (is_lat) {
        nch = 1;
    } else {
        nch = vis * 4 - s * 8;
        if (nch <= 0) return;
        if (nch > 8) nch = 8;
    }

    extern __shared__ uint32_t smw[];
    uint32_t* Qs = smw;                  // [64][36]
    uint32_t* Ps = Qs + ABLK;            // [64][36]
    uint32_t* Ks = Ps + ABLK;            // [2][64][36]
    uint32_t* Vp = Ks + 2 * ABLK;        // [2][64][36] d-major, half2 along j

    const int tid = threadIdx.x, warp = tid >> 5, lane = tid & 31;
    const int qr = lane >> 2, qc = lane & 3;
    const int r0 = warp * 16 + qr;

    // ---- load Q (fp32 -> packed fp16) ----
    #pragma unroll
    for (int it = 0; it < 4; ++it) {
        int e = tid + it * 128;
        int r = e >> 3, c8 = (e & 7) * 8;
        const float* qp = latproj + ((size_t)b * 64 + r) * 1536 + h * 64 + c8;
        float4 v0 = *(const float4*)qp;
        float4 v1 = *(const float4*)(qp + 4);
        uint4 t;
        t.x = pack_h2(v0.x, v0.y); t.y = pack_h2(v0.z, v0.w);
        t.z = pack_h2(v1.x, v1.y); t.w = pack_h2(v1.z, v1.w);
        *(uint4*)&Qs[r * ASTR + (e & 7) * 4] = t;
    }

    const __half* kvb_h = g_kvmed + ((size_t)b * NMEDIA + (size_t)s * 512) * 1024;
    const float*  kvb_f = latproj + (size_t)b * 64 * 1536;
    const int koff_h = h * 64, voff_h = 512 + h * 64;
    const int koff_f = 512 + h * 64, voff_f = 1024 + h * 64;

    // ---- staging: K via cp.async (media) or registers (latent); V via regs ----
    uint4 vreg[4];
    uint4 klreg[4];      // latent-only K registers
    auto cpK = [&](int ch, int buf) {    // media only
        uint32_t* Kb = Ks + buf * ABLK;
        #pragma unroll
        for (int it = 0; it < 4; ++it) {
            int e = tid + it * 128;
            int j = e >> 3, d0 = (e & 7) * 8;
            cp16(&Kb[j * ASTR + (e & 7) * 4],
                 kvb_h + (size_t)(ch * 64 + j) * 1024 + koff_h + d0);
        }
        CP_COMMIT();
    };
    auto loadV = [&](int ch) {
        #pragma unroll
        for (int it = 0; it < 4; ++it) {
            int e = tid + it * 128;
            int j = e >> 3, d0 = (e & 7) * 8;
            if (is_lat) {
                const float* rp = kvb_f + (size_t)j * 1536;
                __half kh[8], vh[8];
                #pragma unroll
                for (int i = 0; i < 8; ++i) {
                    kh[i] = __float2half_rn(rp[koff_f + d0 + i]);
                    vh[i] = __float2half_rn(rp[voff_f + d0 + i]);
                }
                klreg[it] = *(const uint4*)kh;
                vreg[it]  = *(const uint4*)vh;
            } else {
                vreg[it] = *(const uint4*)(kvb_h + (size_t)(ch * 64 + j) * 1024 + voff_h + d0);
            }
        }
    };
    auto storeV = [&](int buf) {
        __half* Vb = (__half*)(Vp + buf * ABLK);
        #pragma unroll
        for (int it = 0; it < 4; ++it) {
            int e = tid + it * 128;
            int j = e >> 3, w4 = e & 7, d0 = w4 * 8;
            const __half* vh = (const __half*)&vreg[it];
            #pragma unroll
            for (int i = 0; i < 8; ++i)
                Vb[(d0 + i) * (2 * ASTR) + j] = vh[i];
            if (is_lat)
                *(uint4*)&Ks[buf * ABLK + j * ASTR + w4 * 4] = klreg[it];
        }
    };

    float m0 = -CUDART_INF_F, m1 = -CUDART_INF_F, l0 = 0.f, l1 = 0.f;
    float o[8][4];
    #pragma unroll
    for (int nf = 0; nf < 8; ++nf)
        #pragma unroll
        for (int r = 0; r < 4; ++r) o[nf][r] = 0.f;

    // prologue: chunk 0
    if (!is_lat) cpK(0, 0);
    loadV(0);
    storeV(0);
    CP_WAIT0();
    __syncthreads();

    for (int ch = 0; ch < nch; ++ch) {
        const int buf = ch & 1;
        const bool nxt = (ch + 1 < nch);
        if (nxt) {                       // issue next chunk's fetches early
            cpK(ch + 1, buf ^ 1);
            loadV(ch + 1);
        }

        const uint32_t* Kb = Ks + buf * ABLK;
        const uint32_t* Vb = Vp + buf * ABLK;

        // ---- S = Q @ K^T ----
        float sacc[8][4] = {};
        #pragma unroll
        for (int ks = 0; ks < 4; ++ks) {
            uint32_t a[4];
            a[0] = Qs[(r0    ) * ASTR + ks * 8 + qc    ];
            a[1] = Qs[(r0 + 8) * ASTR + ks * 8 + qc    ];
            a[2] = Qs[(r0    ) * ASTR + ks * 8 + qc + 4];
            a[3] = Qs[(r0 + 8) * ASTR + ks * 8 + qc + 4];
            #pragma unroll
            for (int nf = 0; nf < 8; ++nf) {
                uint32_t bb[2];
                bb[0] = Kb[(nf * 8 + qr) * ASTR + ks * 8 + qc    ];
                bb[1] = Kb[(nf * 8 + qr) * ASTR + ks * 8 + qc + 4];
                mma_f16(sacc[nf], a, bb);
            }
        }

        // ---- online softmax ----
        float rm0 = -CUDART_INF_F, rm1 = -CUDART_INF_F;
        #pragma unroll
        for (int nf = 0; nf < 8; ++nf) {
            rm0 = fmaxf(rm0, fmaxf(sacc[nf][0], sacc[nf][1]));
            rm1 = fmaxf(rm1, fmaxf(sacc[nf][2], sacc[nf][3]));
        }
        rm0 = fmaxf(rm0, __shfl_xor_sync(0xffffffffu, rm0, 1));
        rm0 = fmaxf(rm0, __shfl_xor_sync(0xffffffffu, rm0, 2));
        rm1 = fmaxf(rm1, __shfl_xor_sync(0xffffffffu, rm1, 1));
        rm1 = fmaxf(rm1, __shfl_xor_sync(0xffffffffu, rm1, 2));
        float mn0 = fmaxf(m0, rm0), mn1 = fmaxf(m1, rm1);
        float cc0 = __expf(m0 - mn0), cc1 = __expf(m1 - mn1);
        float s0 = 0.f, s1 = 0.f;
        #pragma unroll
        for (int nf = 0; nf < 8; ++nf) {
            float p00 = __expf(sacc[nf][0] - mn0);
            float p01 = __expf(sacc[nf][1] - mn0);
            float p10 = __expf(sacc[nf][2] - mn1);
            float p11 = __expf(sacc[nf][3] - mn1);
            s0 += p00 + p01; s1 += p10 + p11;
            Ps[(r0    ) * ASTR + nf * 4 + qc] = pack_h2(p00, p01);
            Ps[(r0 + 8) * ASTR + nf * 4 + qc] = pack_h2(p10, p11);
            o[nf][0] *= cc0; o[nf][1] *= cc0;
            o[nf][2] *= cc1; o[nf][3] *= cc1;
        }
        s0 += __shfl_xor_sync(0xffffffffu, s0, 1);
        s0 += __shfl_xor_sync(0xffffffffu, s0, 2);
        s1 += __shfl_xor_sync(0xffffffffu, s1, 1);
        s1 += __shfl_xor_sync(0xffffffffu, s1, 2);
        m0 = mn0; m1 = mn1;
        l0 = fmaf(l0, cc0, s0);
        l1 = fmaf(l1, cc1, s1);
        __syncwarp();

        // ---- O += P @ V ----
        #pragma unroll
        for (int ks = 0; ks < 4; ++ks) {
            uint32_t a[4];
            a[0] = Ps[(r0    ) * ASTR + ks * 8 + qc    ];
            a[1] = Ps[(r0 + 8) * ASTR + ks * 8 + qc    ];
            a[2] = Ps[(r0    ) * ASTR + ks * 8 + qc + 4];
            a[3] = Ps[(r0 + 8) * ASTR + ks * 8 + qc + 4];
            #pragma unroll
            for (int nf = 0; nf < 8; ++nf) {
                uint32_t bb[2];
                bb[0] = Vb[(nf * 8 + qr) * ASTR + ks * 8 + qc    ];
                bb[1] = Vb[(nf * 8 + qr) * ASTR + ks * 8 + qc + 4];
                mma_f16(o[nf], a, bb);
            }
        }

        if (nxt) {
            storeV(buf ^ 1);             // V into alt buffer
            CP_WAIT0();                  // K cp.async for next chunk done
            __syncthreads();
        }
    }

    // ---- write partials ----
    const size_t pbase = ((size_t)(b * HEADS + h)) * NSP + s;
    float* op = g_opart + pbase * 4096;
    #pragma unroll
    for (int nf = 0; nf < 8; ++nf) {
        *(float2*)&op[(r0    ) * 64 + nf * 8 + qc * 2] = make_float2(o[nf][0], o[nf][1]);
        *(float2*)&op[(r0 + 8) * 64 + nf * 8 + qc * 2] = make_float2(o[nf][2], o[nf][3]);
    }
    if (qc == 0) {
        g_mpart[pbase * 64 + r0    ] = m0;
        g_mpart[pbase * 64 + r0 + 8] = m1;
        g_lpart[pbase * 64 + r0    ] = l0;
        g_lpart[pbase * 64 + r0 + 8] = l1;
    }
}

// ---------------------------------------------------------------------------
// Combine window partials -> attn_out (R14-passing).
// ---------------------------------------------------------------------------
__global__ void __launch_bounds__(256)
attn_combine(const int* __restrict__ indices, float* __restrict__ attn_out)
{
    const int bh = blockIdx.x;
    const int b = bh >> 3, h = bh & 7;
    const int visw = (indices[b] + 1) >> 1;
    const int warp = threadIdx.x >> 5, lane = threadIdx.x & 31;
    const int i = blockIdx.y * 8 + warp;

    __shared__ float ws[8][17];
    __shared__ float linv[8];

    const size_t base = (size_t)bh * NSP;

    float m    = (lane < visw) ? g_mpart[(base + lane) * 64 + i] : -CUDART_INF_F;
    float mlat = g_mpart[(base + 16) * 64 + i];
    float mm = fmaxf(m, mlat);
    #pragma unroll
    for (int o = 16; o > 0; o >>= 1)
        mm = fmaxf(mm, __shfl_xor_sync(0xffffffffu, mm, o));

    float w  = (lane < visw) ? __expf(m - mm) : 0.f;
    float wl = __expf(mlat - mm);
    float l  = (lane < visw) ? g_lpart[(base + lane) * 64 + i] * w : 0.f;
    #pragma unroll
    for (int o = 16; o > 0; o >>= 1)
        l += __shfl_xor_sync(0xffffffffu, l, o);
    float ll = g_lpart[(base + 16) * 64 + i] * wl;

    if (lane < 16) ws[warp][lane] = w;
    if (lane == 0) {
        ws[warp][16] = wl;
        linv[warp] = 1.f / (l + ll);
    }
    __syncwarp();

    const int d = lane * 2;
    float2 v = *(const float2*)(g_opart + (base + 16) * 4096 + i * 64 + d);
    float a0 = v.x * ws[warp][16];
    float a1 = v.y * ws[warp][16];
    for (int s = 0; s < visw; ++s) {
        float wv = ws[warp][s];
        float2 u = *(const float2*)(g_opart + (base + s) * 4096 + i * 64 + d);
        a0 = fmaf(u.x, wv, a0);
        a1 = fmaf(u.y, wv, a1);
    }
    float li = linv[warp];
    *(float2*)(attn_out + ((size_t)b * 64 + i) * 512 + h * 64 + d) =
        make_float2(a0 * li, a1 * li);
}

// ---------------------------------------------------------------------------
// Launch
// ---------------------------------------------------------------------------
extern "C" void kernel_launch(void* const* d_in, const int* in_sizes, int n_in,
                              void* d_out, int out_size)
{
    (void)in_sizes; (void)n_in; (void)out_size;
    const float* x    = (const float*)d_in[0];
    const float* lat  = (const float*)d_in[1];
    const int*   idx  = (const int*)  d_in[2];
    const float* g_m  = (const float*)d_in[3];
    const float* b_m  = (const float*)d_in[4];
    const float* g_l  = (const float*)d_in[5];
    const float* b_l  = (const float*)d_in[6];
    const float* Wq   = (const float*)d_in[7];
    const float* bq   = (const float*)d_in[8];
    const float* Wkv  = (const float*)d_in[9];
    const float* bkv  = (const float*)d_in[10];
    const float* Wo   = (const float*)d_in[11];
    const float* bo   = (const float*)d_in[12];
    float* out = (float*)d_out;

    void *plp, *pattno;
    cudaGetSymbolAddress(&plp,    g_latproj);
    cudaGetSymbolAddress(&pattno, g_attno);

    cudaFuncSetAttribute(gemm_big,
                         cudaFuncAttributeMaxDynamicSharedMemorySize, BIG_SMEM);
    cudaFuncSetAttribute(gemm_out,
                         cudaFuncAttributeMaxDynamicSharedMemorySize, OUT_SMEM);
    cudaFuncSetAttribute(attn_split_f16,
                         cudaFuncAttributeMaxDynamicSharedMemorySize, ATTN_SMEM);

    // weight + column-vector prep
    prep_w<<<dim3(16, 8, 4), 256>>>(Wq, Wkv, Wo, g_l, g_m);
    prep_c<<<40, 256>>>(Wq, Wkv, bq, bkv, b_l, b_m);

    // unified media-KV (fp16 out) + latent projections (K-chunk 64)
    gemm_big<<<2072, 256, BIG_SMEM>>>(x, lat, idx);

    // attention (512-token windows, cp.async K) + combine
    attn_split_f16<<<dim3(NSP, HEADS, BATCH), 128, ATTN_SMEM>>>(
        (const float*)plp, idx);
    attn_combine<<<dim3(64, 8), 256>>>(idx, (float*)pattno);

    // output projection
    gemm_out<<<16, 256, OUT_SMEM>>>((const float*)pattno, bo, out);
}